// round 13
// baseline (speedup 1.0000x reference)
#include <cuda_runtime.h>
#include <math.h>

// ---------------- sizes ----------------
#define B_    16
#define L_    1024
#define DM    128
#define DI    256
#define MTOT  (B_*L_)      // 16384 rows
#define NSEG  128
#define LSEG  8
#define GSLAB 32

// ---------------- scratch (device globals; no allocation) ----------------
__device__ float g_fused[MTOT*DM];
__device__ float g_h    [MTOT*DM];
__device__ float g_xz   [MTOT*2*DI];      // [0,256)=xm_pre, [256,512)=z
__device__ float g_xm   [MTOT*DI];
__device__ float g_xdbl [MTOT*24];
__device__ float g_y    [MTOT*DI];
__device__ float g_agg  [B_*DI*NSEG*16];  // [b][d][seg][P8|H8]
__device__ float g_img  [B_*DM*1024];     // NCHW (16,128,32,32)
__device__ float g_c1   [B_*64*64*64];
__device__ float g_c2   [B_*32*128*128];
__device__ float g_w1c  [64*128*16];
__device__ float g_w2c  [32*64*16];
__device__ float g_gp   [2*16*GSLAB*64];

// ---------------- LayerNorm (warp per row of 128) ----------------
__global__ void ln_kernel(const float* __restrict__ x, const float* __restrict__ gam,
                          const float* __restrict__ bet, float* __restrict__ out) {
    int gw   = (blockIdx.x * blockDim.x + threadIdx.x) >> 5;
    int lane = threadIdx.x & 31;
    float4 v = *reinterpret_cast<const float4*>(x + (size_t)gw*128 + lane*4);
    float s  = v.x + v.y + v.z + v.w;
    float ss = v.x*v.x + v.y*v.y + v.z*v.z + v.w*v.w;
    #pragma unroll
    for (int o = 16; o; o >>= 1) {
        s  += __shfl_xor_sync(0xffffffffu, s,  o);
        ss += __shfl_xor_sync(0xffffffffu, ss, o);
    }
    float mean = s * (1.f/128.f);
    float var  = ss * (1.f/128.f) - mean*mean;
    float r    = rsqrtf(var + 1e-5f);
    float4 g4  = *reinterpret_cast<const float4*>(gam + lane*4);
    float4 b4  = *reinterpret_cast<const float4*>(bet + lane*4);
    float4 o4;
    o4.x = (v.x-mean)*r*g4.x + b4.x;
    o4.y = (v.y-mean)*r*g4.y + b4.y;
    o4.z = (v.z-mean)*r*g4.z + b4.z;
    o4.w = (v.w-mean)*r*g4.w + b4.w;
    *reinterpret_cast<float4*>(out + (size_t)gw*128 + lane*4) = o4;
}

__global__ void ln_final_kernel(const float* __restrict__ x, const float* __restrict__ gam,
                                const float* __restrict__ bet) {
    int gw   = (blockIdx.x * blockDim.x + threadIdx.x) >> 5;
    int lane = threadIdx.x & 31;
    float4 v = *reinterpret_cast<const float4*>(x + (size_t)gw*128 + lane*4);
    float s  = v.x + v.y + v.z + v.w;
    float ss = v.x*v.x + v.y*v.y + v.z*v.z + v.w*v.w;
    #pragma unroll
    for (int o = 16; o; o >>= 1) {
        s  += __shfl_xor_sync(0xffffffffu, s,  o);
        ss += __shfl_xor_sync(0xffffffffu, ss, o);
    }
    float mean = s * (1.f/128.f);
    float var  = ss * (1.f/128.f) - mean*mean;
    float r    = rsqrtf(var + 1e-5f);
    float4 g4  = *reinterpret_cast<const float4*>(gam + lane*4);
    float4 b4  = *reinterpret_cast<const float4*>(bet + lane*4);
    int b = gw >> 10, l = gw & 1023;
    size_t base = ((size_t)b*128 + lane*4)*1024 + l;
    g_img[base + 0*1024] = (v.x-mean)*r*g4.x + b4.x;
    g_img[base + 1*1024] = (v.y-mean)*r*g4.y + b4.y;
    g_img[base + 2*1024] = (v.z-mean)*r*g4.z + b4.z;
    g_img[base + 3*1024] = (v.w-mean)*r*g4.w + b4.w;
}

// ---------------- SGEMM 128x128x16: C[M,N] = A[M,K] @ W[N,K]^T (in_proj) ----------------
__global__ __launch_bounds__(256, 2) void sgemm128(const float* __restrict__ A,
        const float* __restrict__ W, float* __restrict__ C, int N, int K) {
    __shared__ float As[16][128];
    __shared__ float Bs[16][128];
    const int tid = threadIdx.x;
    const int m0 = blockIdx.y * 128, n0 = blockIdx.x * 128;
    const int tx = tid & 15, ty = tid >> 4;
    const int lr = tid >> 1, lc = (tid & 1) * 8;
    float acc[8][8];
    #pragma unroll
    for (int i = 0; i < 8; i++)
        #pragma unroll
        for (int j = 0; j < 8; j++) acc[i][j] = 0.f;

    const float* Ap = A + (size_t)(m0 + lr)*K + lc;
    const float* Wp = W + (size_t)(n0 + lr)*K + lc;

    for (int k0 = 0; k0 < K; k0 += 16) {
        float4 a0 = *reinterpret_cast<const float4*>(Ap + k0);
        float4 a1 = *reinterpret_cast<const float4*>(Ap + k0 + 4);
        float4 b0 = *reinterpret_cast<const float4*>(Wp + k0);
        float4 b1 = *reinterpret_cast<const float4*>(Wp + k0 + 4);
        __syncthreads();
        As[lc+0][lr]=a0.x; As[lc+1][lr]=a0.y; As[lc+2][lr]=a0.z; As[lc+3][lr]=a0.w;
        As[lc+4][lr]=a1.x; As[lc+5][lr]=a1.y; As[lc+6][lr]=a1.z; As[lc+7][lr]=a1.w;
        Bs[lc+0][lr]=b0.x; Bs[lc+1][lr]=b0.y; Bs[lc+2][lr]=b0.z; Bs[lc+3][lr]=b0.w;
        Bs[lc+4][lr]=b1.x; Bs[lc+5][lr]=b1.y; Bs[lc+6][lr]=b1.z; Bs[lc+7][lr]=b1.w;
        __syncthreads();
        #pragma unroll
        for (int k = 0; k < 16; k++) {
            float4 af0 = *reinterpret_cast<const float4*>(&As[k][ty*8]);
            float4 af1 = *reinterpret_cast<const float4*>(&As[k][ty*8+4]);
            float4 bf0 = *reinterpret_cast<const float4*>(&Bs[k][tx*8]);
            float4 bf1 = *reinterpret_cast<const float4*>(&Bs[k][tx*8+4]);
            float av[8] = {af0.x,af0.y,af0.z,af0.w,af1.x,af1.y,af1.z,af1.w};
            float bv[8] = {bf0.x,bf0.y,bf0.z,bf0.w,bf1.x,bf1.y,bf1.z,bf1.w};
            #pragma unroll
            for (int i = 0; i < 8; i++)
                #pragma unroll
                for (int j = 0; j < 8; j++)
                    acc[i][j] = fmaf(av[i], bv[j], acc[i][j]);
        }
    }
    #pragma unroll
    for (int i = 0; i < 8; i++) {
        size_t row = (size_t)(m0 + ty*8 + i)*N + n0 + tx*8;
        *reinterpret_cast<float4*>(C + row)     = make_float4(acc[i][0], acc[i][1], acc[i][2], acc[i][3]);
        *reinterpret_cast<float4*>(C + row + 4) = make_float4(acc[i][4], acc[i][5], acc[i][6], acc[i][7]);
    }
}

// ---------------- out_proj + residual + (next) LayerNorm fused ----------------
__global__ __launch_bounds__(256, 2) void sgemm_out_ln(const float* __restrict__ A,
        const float* __restrict__ W, const float* __restrict__ skip,
        const float* __restrict__ gam, const float* __restrict__ bet,
        float* __restrict__ fused_out, float* __restrict__ h_out, int mode) {
    const int K = 256, N = 128;
    __shared__ float As[16][128];
    __shared__ float Bs[16][128];
    const int tid = threadIdx.x;
    const int m0 = blockIdx.x * 128;
    const int tx = tid & 15, ty = tid >> 4;
    const int lr = tid >> 1, lc = (tid & 1) * 8;
    float acc[8][8];
    #pragma unroll
    for (int i = 0; i < 8; i++)
        #pragma unroll
        for (int j = 0; j < 8; j++) acc[i][j] = 0.f;

    const float* Ap = A + (size_t)(m0 + lr)*K + lc;
    const float* Wp = W + (size_t)lr*K + lc;

    for (int k0 = 0; k0 < K; k0 += 16) {
        float4 a0 = *reinterpret_cast<const float4*>(Ap + k0);
        float4 a1 = *reinterpret_cast<const float4*>(Ap + k0 + 4);
        float4 b0 = *reinterpret_cast<const float4*>(Wp + k0);
        float4 b1 = *reinterpret_cast<const float4*>(Wp + k0 + 4);
        __syncthreads();
        As[lc+0][lr]=a0.x; As[lc+1][lr]=a0.y; As[lc+2][lr]=a0.z; As[lc+3][lr]=a0.w;
        As[lc+4][lr]=a1.x; As[lc+5][lr]=a1.y; As[lc+6][lr]=a1.z; As[lc+7][lr]=a1.w;
        Bs[lc+0][lr]=b0.x; Bs[lc+1][lr]=b0.y; Bs[lc+2][lr]=b0.z; Bs[lc+3][lr]=b0.w;
        Bs[lc+4][lr]=b1.x; Bs[lc+5][lr]=b1.y; Bs[lc+6][lr]=b1.z; Bs[lc+7][lr]=b1.w;
        __syncthreads();
        #pragma unroll
        for (int k = 0; k < 16; k++) {
            float4 af0 = *reinterpret_cast<const float4*>(&As[k][ty*8]);
            float4 af1 = *reinterpret_cast<const float4*>(&As[k][ty*8+4]);
            float4 bf0 = *reinterpret_cast<const float4*>(&Bs[k][tx*8]);
            float4 bf1 = *reinterpret_cast<const float4*>(&Bs[k][tx*8+4]);
            float av[8] = {af0.x,af0.y,af0.z,af0.w,af1.x,af1.y,af1.z,af1.w};
            float bv[8] = {bf0.x,bf0.y,bf0.z,bf0.w,bf1.x,bf1.y,bf1.z,bf1.w};
            #pragma unroll
            for (int i = 0; i < 8; i++)
                #pragma unroll
                for (int j = 0; j < 8; j++)
                    acc[i][j] = fmaf(av[i], bv[j], acc[i][j]);
        }
    }
    float4 g0 = make_float4(0,0,0,0), g1 = g0, be0 = g0, be1 = g0;
    if (mode == 0) {
        g0  = *reinterpret_cast<const float4*>(gam + tx*8);
        g1  = *reinterpret_cast<const float4*>(gam + tx*8 + 4);
        be0 = *reinterpret_cast<const float4*>(bet + tx*8);
        be1 = *reinterpret_cast<const float4*>(bet + tx*8 + 4);
    }
    #pragma unroll
    for (int i = 0; i < 8; i++) {
        size_t row = (size_t)(m0 + ty*8 + i)*N + tx*8;
        float4 s0 = *reinterpret_cast<const float4*>(skip + row);
        float4 s1 = *reinterpret_cast<const float4*>(skip + row + 4);
        float v[8];
        v[0]=acc[i][0]+s0.x; v[1]=acc[i][1]+s0.y; v[2]=acc[i][2]+s0.z; v[3]=acc[i][3]+s0.w;
        v[4]=acc[i][4]+s1.x; v[5]=acc[i][5]+s1.y; v[6]=acc[i][6]+s1.z; v[7]=acc[i][7]+s1.w;
        *reinterpret_cast<float4*>(fused_out + row)     = make_float4(v[0],v[1],v[2],v[3]);
        *reinterpret_cast<float4*>(fused_out + row + 4) = make_float4(v[4],v[5],v[6],v[7]);
        if (mode == 0) {
            float s = 0.f, ss = 0.f;
            #pragma unroll
            for (int j = 0; j < 8; j++) { s += v[j]; ss += v[j]*v[j]; }
            #pragma unroll
            for (int o = 1; o < 16; o <<= 1) {
                s  += __shfl_xor_sync(0xffffffffu, s,  o);
                ss += __shfl_xor_sync(0xffffffffu, ss, o);
            }
            float mean = s * (1.f/128.f);
            float var  = ss * (1.f/128.f) - mean*mean;
            float r    = rsqrtf(var + 1e-5f);
            float h[8];
            h[0]=(v[0]-mean)*r*g0.x+be0.x; h[1]=(v[1]-mean)*r*g0.y+be0.y;
            h[2]=(v[2]-mean)*r*g0.z+be0.z; h[3]=(v[3]-mean)*r*g0.w+be0.w;
            h[4]=(v[4]-mean)*r*g1.x+be1.x; h[5]=(v[5]-mean)*r*g1.y+be1.y;
            h[6]=(v[6]-mean)*r*g1.z+be1.z; h[7]=(v[7]-mean)*r*g1.w+be1.w;
            *reinterpret_cast<float4*>(h_out + row)     = make_float4(h[0],h[1],h[2],h[3]);
            *reinterpret_cast<float4*>(h_out + row + 4) = make_float4(h[4],h[5],h[6],h[7]);
        }
    }
}

// ---------------- xproj dedicated: C[16384,24] = xm @ W^T (32-row blocks, smem) ----------------
#define XP_SMEM ((24*260 + 32*260)*4)
__global__ __launch_bounds__(256) void xproj_kernel(const float* __restrict__ A,
        const float* __restrict__ W, float* __restrict__ C) {
    extern __shared__ float xsh[];
    float* sW = xsh;            // [24][260]
    float* sA = xsh + 24*260;   // [32][260]
    int tid = threadIdx.x;
    int m0 = blockIdx.x * 32;
    for (int i = tid; i < 24*256; i += 256) {
        int c = i >> 8, k = i & 255;
        sW[c*260 + k] = W[i];
    }
    for (int i = tid; i < 32*256; i += 256) {
        int r = i >> 8, k = i & 255;
        sA[r*260 + k] = A[(size_t)(m0 + r)*256 + k];
    }
    __syncthreads();
    int r  = tid >> 3;
    int c0 = (tid & 7) * 3;
    float acc0 = 0.f, acc1 = 0.f, acc2 = 0.f;
    #pragma unroll 4
    for (int k = 0; k < 256; k += 4) {
        float4 a  = *reinterpret_cast<const float4*>(&sA[r*260 + k]);
        float4 w0 = *reinterpret_cast<const float4*>(&sW[(c0+0)*260 + k]);
        float4 w1 = *reinterpret_cast<const float4*>(&sW[(c0+1)*260 + k]);
        float4 w2 = *reinterpret_cast<const float4*>(&sW[(c0+2)*260 + k]);
        acc0 = fmaf(a.x, w0.x, acc0); acc0 = fmaf(a.y, w0.y, acc0);
        acc0 = fmaf(a.z, w0.z, acc0); acc0 = fmaf(a.w, w0.w, acc0);
        acc1 = fmaf(a.x, w1.x, acc1); acc1 = fmaf(a.y, w1.y, acc1);
        acc1 = fmaf(a.z, w1.z, acc1); acc1 = fmaf(a.w, w1.w, acc1);
        acc2 = fmaf(a.x, w2.x, acc2); acc2 = fmaf(a.y, w2.y, acc2);
        acc2 = fmaf(a.z, w2.z, acc2); acc2 = fmaf(a.w, w2.w, acc2);
    }
    size_t o = (size_t)(m0 + r)*24 + c0;
    C[o+0] = acc0; C[o+1] = acc1; C[o+2] = acc2;
}

// ---------------- depthwise causal conv1d (k=4) + bias + SiLU ----------------
__global__ void dwconv_silu_kernel(const float* __restrict__ w, const float* __restrict__ bias) {
    int idx = blockIdx.x * blockDim.x + threadIdx.x;
    int d = idx & (DI-1);
    int m = idx >> 8;
    int l = m & 1023;
    float acc = bias[d];
    #pragma unroll
    for (int k = 0; k < 4; k++) {
        int ll = l + k - 3;
        if (ll >= 0) acc = fmaf(w[d*4 + k], g_xz[(size_t)(m + k - 3)*512 + d], acc);
    }
    g_xm[idx] = acc * __frcp_rn(1.f + __expf(-acc));
}

// ---------------- dt/w1 helper ----------------
__device__ __forceinline__ void dt_w1(float acc, float& dt, float& w1) {
    float e = __expf(acc);
    w1 = __frcp_rn(1.f + e);
    dt = (acc > 20.f) ? acc : __logf(1.f + e);
}

// ---------------- scan pass1 (LSEG=8) ----------------
__global__ __launch_bounds__(256) void scan_pass1(const float* __restrict__ Alog,
        const float* __restrict__ dtw, const float* __restrict__ dtb) {
    __shared__ float sA[2048], sW[2048], sB[256];
    int tid = threadIdx.x;
    for (int i = tid; i < 2048; i += 256) { sA[i] = -expf(Alog[i]); sW[i] = dtw[i]; }
    sB[tid] = dtb[tid];
    __syncthreads();
    int d = tid, seg = blockIdx.x, b = blockIdx.y;
    float A[8], wj[8];
    bool fast = true;
    #pragma unroll
    for (int n = 0; n < 8; n++) {
        A[n] = sA[d*8+n]; wj[n] = sW[d*8+n];
        fast = fast && (fabsf(A[n] + (float)(n+1)) < 1e-3f*(float)(n+1));
    }
    float bt = sB[d];
    float P[8], H[8];
    #pragma unroll
    for (int n = 0; n < 8; n++) { P[n] = 1.f; H[n] = 0.f; }
    int m0 = (b << 10) + (seg << 3);
    #pragma unroll 2
    for (int l = 0; l < LSEG; l++) {
        int m = m0 + l;
        float u = g_xm[(size_t)m*256 + d];
        const float* r = g_xdbl + (size_t)m*24;
        float acc = bt;
        #pragma unroll
        for (int j = 0; j < 8; j++) acc = fmaf(__ldg(r + j), wj[j], acc);
        float dt, w1;
        dt_w1(acc, dt, w1);
        float p[8];
        if (fast) {
            p[0] = w1;
            #pragma unroll
            for (int n = 1; n < 8; n++) p[n] = p[n-1]*w1;
        } else {
            #pragma unroll
            for (int n = 0; n < 8; n++) p[n] = __expf(dt*A[n]);
        }
        float du = dt * u;
        float4 B0 = *reinterpret_cast<const float4*>(r + 8);
        float4 B1 = *reinterpret_cast<const float4*>(r + 12);
        float Bv[8] = {B0.x,B0.y,B0.z,B0.w,B1.x,B1.y,B1.z,B1.w};
        #pragma unroll
        for (int n = 0; n < 8; n++) {
            P[n] *= p[n];
            H[n] = fmaf(p[n], H[n], du * Bv[n]);
        }
    }
    size_t base = ((size_t)((b*256 + d))*NSEG + seg) * 16;
    float4* o = reinterpret_cast<float4*>(g_agg + base);
    o[0] = make_float4(P[0],P[1],P[2],P[3]);
    o[1] = make_float4(P[4],P[5],P[6],P[7]);
    o[2] = make_float4(H[0],H[1],H[2],H[3]);
    o[3] = make_float4(H[4],H[5],H[6],H[7]);
}

// ---------------- scan pass2: warp-scan, lane owns 4 segments (NSEG=128) ----------------
__global__ __launch_bounds__(256) void scan_pass2() {
    int wid = threadIdx.x >> 5, lane = threadIdx.x & 31;
    size_t pair = (size_t)blockIdx.x * 8 + wid;          // 4096 pairs, grid 512
    float4* base = reinterpret_cast<float4*>(g_agg + pair * (NSEG*16));
    float P[4][8], H[4][8];
    #pragma unroll
    for (int q = 0; q < 4; q++) {
        int s = lane*4 + q;
        float4 p0 = base[s*4+0], p1 = base[s*4+1];
        float4 h0 = base[s*4+2], h1 = base[s*4+3];
        P[q][0]=p0.x; P[q][1]=p0.y; P[q][2]=p0.z; P[q][3]=p0.w;
        P[q][4]=p1.x; P[q][5]=p1.y; P[q][6]=p1.z; P[q][7]=p1.w;
        H[q][0]=h0.x; H[q][1]=h0.y; H[q][2]=h0.z; H[q][3]=h0.w;
        H[q][4]=h1.x; H[q][5]=h1.y; H[q][6]=h1.z; H[q][7]=h1.w;
    }
    // combine 4 ops (op0 applied first)
    float Pc[8], Hc[8];
    #pragma unroll
    for (int n = 0; n < 8; n++) { Pc[n] = P[0][n]; Hc[n] = H[0][n]; }
    #pragma unroll
    for (int q = 1; q < 4; q++)
        #pragma unroll
        for (int n = 0; n < 8; n++) {
            Hc[n] = fmaf(P[q][n], Hc[n], H[q][n]);
            Pc[n] *= P[q][n];
        }
    // inclusive warp scan over combined ops
    #pragma unroll
    for (int dd = 1; dd < 32; dd <<= 1) {
        #pragma unroll
        for (int n = 0; n < 8; n++) {
            float po = __shfl_up_sync(0xffffffffu, Pc[n], dd);
            float ho = __shfl_up_sync(0xffffffffu, Hc[n], dd);
            if (lane >= dd) { Hc[n] = fmaf(Pc[n], ho, Hc[n]); Pc[n] *= po; }
        }
    }
    // exclusive prefix state for this lane's first segment
    float h[8];
    #pragma unroll
    for (int n = 0; n < 8; n++) {
        float hh = __shfl_up_sync(0xffffffffu, Hc[n], 1);
        h[n] = (lane == 0) ? 0.f : hh;
    }
    // write per-segment prefix states, chaining through lane-local ops
    #pragma unroll
    for (int q = 0; q < 4; q++) {
        int s = lane*4 + q;
        base[s*4+2] = make_float4(h[0],h[1],h[2],h[3]);
        base[s*4+3] = make_float4(h[4],h[5],h[6],h[7]);
        #pragma unroll
        for (int n = 0; n < 8; n++) h[n] = fmaf(P[q][n], h[n], H[q][n]);
    }
}

// ---------------- scan pass3 (LSEG=8) ----------------
__global__ __launch_bounds__(256) void scan_pass3(const float* __restrict__ Alog,
        const float* __restrict__ dtw, const float* __restrict__ dtb,
        const float* __restrict__ Dp) {
    __shared__ float sA[2048], sW[2048], sB[256], sD[256];
    int tid = threadIdx.x;
    for (int i = tid; i < 2048; i += 256) { sA[i] = -expf(Alog[i]); sW[i] = dtw[i]; }
    sB[tid] = dtb[tid];
    sD[tid] = Dp[tid];
    __syncthreads();
    int d = tid, seg = blockIdx.x, b = blockIdx.y;
    float A[8], wj[8];
    bool fast = true;
    #pragma unroll
    for (int n = 0; n < 8; n++) {
        A[n] = sA[d*8+n]; wj[n] = sW[d*8+n];
        fast = fast && (fabsf(A[n] + (float)(n+1)) < 1e-3f*(float)(n+1));
    }
    float bt = sB[d], Dd = sD[d];
    size_t base = ((size_t)((b*256 + d))*NSEG + seg) * 16;
    float4 h0 = *reinterpret_cast<const float4*>(g_agg + base + 8);
    float4 h1 = *reinterpret_cast<const float4*>(g_agg + base + 12);
    float h[8] = {h0.x,h0.y,h0.z,h0.w,h1.x,h1.y,h1.z,h1.w};
    int m0 = (b << 10) + (seg << 3);
    #pragma unroll 2
    for (int l = 0; l < LSEG; l++) {
        int m = m0 + l;
        float u = g_xm[(size_t)m*256 + d];
        const float* r = g_xdbl + (size_t)m*24;
        float acc = bt;
        #pragma unroll
        for (int j = 0; j < 8; j++) acc = fmaf(__ldg(r + j), wj[j], acc);
        float dt, w1;
        dt_w1(acc, dt, w1);
        float p[8];
        if (fast) {
            p[0] = w1;
            #pragma unroll
            for (int n = 1; n < 8; n++) p[n] = p[n-1]*w1;
        } else {
            #pragma unroll
            for (int n = 0; n < 8; n++) p[n] = __expf(dt*A[n]);
        }
        float du = dt * u;
        float4 B0 = *reinterpret_cast<const float4*>(r + 8);
        float4 B1 = *reinterpret_cast<const float4*>(r + 12);
        float4 C0 = *reinterpret_cast<const float4*>(r + 16);
        float4 C1 = *reinterpret_cast<const float4*>(r + 20);
        float Bv[8] = {B0.x,B0.y,B0.z,B0.w,B1.x,B1.y,B1.z,B1.w};
        float Cv[8] = {C0.x,C0.y,C0.z,C0.w,C1.x,C1.y,C1.z,C1.w};
        float ys0 = 0.f, ys1 = 0.f;
        #pragma unroll
        for (int n = 0; n < 8; n++) {
            h[n] = fmaf(p[n], h[n], du * Bv[n]);
            if (n & 1) ys1 = fmaf(h[n], Cv[n], ys1);
            else       ys0 = fmaf(h[n], Cv[n], ys0);
        }
        float z  = g_xz[(size_t)m*512 + 256 + d];
        float sz = z * __frcp_rn(1.f + __expf(-z));
        g_y[(size_t)m*256 + d] = (ys0 + ys1 + u*Dd) * sz;
    }
}

// ---------------- combined 2x2 weights ----------------
__global__ void make_wc_kernel(const float* __restrict__ w, float* __restrict__ wc, int total) {
    int i = blockIdx.x * 256 + threadIdx.x;
    if (i >= total) return;
    const float* ws = w + (size_t)i*9;
    float t[3][4];
    #pragma unroll
    for (int ky = 0; ky < 3; ky++) {
        float w0 = ws[ky*3+0], w1 = ws[ky*3+1], w2 = ws[ky*3+2];
        t[ky][0] = w0;
        t[ky][1] = w1 + w2;
        t[ky][2] = w0 + w1;
        t[ky][3] = w2;
    }
    float* o = wc + (size_t)i*16;
    #pragma unroll
    for (int bk = 0; bk < 2; bk++) {
        o[(0*2+bk)*4 + 0*2 + 0] = t[0][bk*2+0];
        o[(0*2+bk)*4 + 0*2 + 1] = t[0][bk*2+1];
        o[(0*2+bk)*4 + 1*2 + 0] = t[1][bk*2+0] + t[2][bk*2+0];
        o[(0*2+bk)*4 + 1*2 + 1] = t[1][bk*2+1] + t[2][bk*2+1];
        o[(1*2+bk)*4 + 0*2 + 0] = t[0][bk*2+0] + t[1][bk*2+0];
        o[(1*2+bk)*4 + 0*2 + 1] = t[0][bk*2+1] + t[1][bk*2+1];
        o[(1*2+bk)*4 + 1*2 + 0] = t[2][bk*2+0];
        o[(1*2+bk)*4 + 1*2 + 1] = t[2][bk*2+1];
    }
}

// ---------------- up2+3x3 conv via 2x2 combined weights (R2 winner) ----------------
template<int CI, int CO, int SRCD, int OUTD, int MODE>
__global__ __launch_bounds__(256) void conv_up2_kernel(
        const float* __restrict__ in, float* __restrict__ out,
        const float* __restrict__ Wc, const float* __restrict__ bias,
        const float* __restrict__ bng, const float* __restrict__ bnb,
        const float* __restrict__ bnm, const float* __restrict__ bnv) {
    __shared__ float s_x[16][18][18];
    __shared__ float s_w[2048];
    const int tid = threadIdx.x;
    const int b   = blockIdx.z;
    const int cog = blockIdx.y;
    const int ntx = OUTD / 32;
    const int tyi = blockIdx.x / ntx, txi = blockIdx.x % ntx;
    const int oy0 = tyi*32, ox0 = txi*32;
    const int sy0 = oy0/2 - 1, sx0 = ox0/2 - 1;
    const int px = tid & 15, py = tid >> 4;
    const int pa = py & 1, pb = px & 1;
    const int p  = pa*2 + pb;

    int rbase[2], cbase[2];
    #pragma unroll
    for (int i = 0; i < 2; i++) {
        rbase[i] = ((py + 16*i) >> 1) + pa;
        cbase[i] = ((px + 16*i) >> 1) + pb;
    }

    float acc[8][4];
    #pragma unroll
    for (int c = 0; c < 8; c++)
        #pragma unroll
        for (int q = 0; q < 4; q++) acc[c][q] = 0.f;

    for (int cc = 0; cc < CI; cc += 16) {
        for (int idx = tid; idx < 16*324; idx += 256) {
            int ci = idx / 324; int rem = idx - ci*324;
            int r = rem / 18, c = rem - r*18;
            int sy = sy0 + r, sxp = sx0 + c;
            float v = 0.f;
            if (sy >= 0 && sy < SRCD && sxp >= 0 && sxp < SRCD)
                v = in[(((size_t)b*CI + cc + ci)*SRCD + sy)*SRCD + sxp];
            s_x[ci][r][c] = v;
        }
        for (int i = tid; i < 2048; i += 256) {
            int ci = i >> 7, rem = i & 127;
            int pp = rem >> 5, co = (rem >> 2) & 7, jk = i & 3;
            s_w[i] = Wc[((size_t)(cog*8 + co)*CI + cc + ci)*16 + pp*4 + jk];
        }
        __syncthreads();
        #pragma unroll 2
        for (int ci = 0; ci < 16; ci++) {
            float4 w4[8];
            #pragma unroll
            for (int co = 0; co < 8; co++)
                w4[co] = *reinterpret_cast<const float4*>(&s_w[((ci*4 + p)*8 + co)*4]);
            #pragma unroll
            for (int iq = 0; iq < 2; iq++)
                #pragma unroll
                for (int jq = 0; jq < 2; jq++) {
                    int q = iq*2 + jq;
                    float x00 = s_x[ci][rbase[iq]+0][cbase[jq]+0];
                    float x01 = s_x[ci][rbase[iq]+0][cbase[jq]+1];
                    float x10 = s_x[ci][rbase[iq]+1][cbase[jq]+0];
                    float x11 = s_x[ci][rbase[iq]+1][cbase[jq]+1];
                    #pragma unroll
                    for (int co = 0; co < 8; co++) {
                        float a = acc[co][q];
                        a = fmaf(w4[co].x, x00, a);
                        a = fmaf(w4[co].y, x01, a);
                        a = fmaf(w4[co].z, x10, a);
                        a = fmaf(w4[co].w, x11, a);
                        acc[co][q] = a;
                    }
                }
        }
        __syncthreads();
    }
    #pragma unroll
    for (int co = 0; co < 8; co++) {
        int c = cog*8 + co;
        float sc = bng[c] * rsqrtf(bnv[c] + 1e-5f);
        float sh2 = bnb[c] - bnm[c]*sc;
        float bsv = bias[c];
        #pragma unroll
        for (int q = 0; q < 4; q++) {
            int i = q >> 1, j = q & 1;
            int oy = oy0 + py + 16*i, ox = ox0 + px + 16*j;
            float v = acc[co][q] + bsv;
            v = (MODE == 1) ? fmaxf(v*sc + sh2, 0.f) : (fmaxf(v, 0.f)*sc + sh2);
            out[(((size_t)b*CO + c)*OUTD + oy)*OUTD + ox] = v;
        }
    }
}

// ---------------- CCE gate partials (R11/R12) ----------------
__global__ __launch_bounds__(256) void cce_gate_part(const float* __restrict__ w1,
        const float* __restrict__ ox, const float* __restrict__ oy) {
    __shared__ float sw[1024];
    __shared__ float sx[64*36];
    __shared__ float red[2][8][32];
    int tid = threadIdx.x;
    for (int i = tid; i < 1024; i += 256) sw[i] = w1[i];
    __syncthreads();
    int which = blockIdx.z, b = blockIdx.y, slab = blockIdx.x;
    const float* base = (which ? oy : ox) + (size_t)b*32*16384;
    int c = tid & 31, g = tid >> 5;
    float4 w4[8];
    #pragma unroll
    for (int q = 0; q < 8; q++)
        w4[q] = *reinterpret_cast<const float4*>(&sw[c*32 + q*4]);
    float mx = -1e30f, sm = 0.f;
    int p0 = slab * (16384/GSLAB);
    #pragma unroll 1
    for (int it = 0; it < (16384/GSLAB)/64; it++) {
        int pt = p0 + it*64;
        __syncthreads();
        for (int i = tid; i < 512; i += 256) {
            int ci = i >> 4, p4 = (i & 15) * 4;
            float4 v = *reinterpret_cast<const float4*>(base + (size_t)ci*16384 + pt + p4);
            sx[(p4+0)*36 + ci] = v.x;
            sx[(p4+1)*36 + ci] = v.y;
            sx[(p4+2)*36 + ci] = v.z;
            sx[(p4+3)*36 + ci] = v.w;
        }
        __syncthreads();
        #pragma unroll
        for (int pp = 0; pp < 8; pp++) {
            const float* xr = &sx[(g*8 + pp)*36];
            float a = 0.f;
            #pragma unroll
            for (int q = 0; q < 8; q++) {
                float4 xv = *reinterpret_cast<const float4*>(xr + q*4);
                a = fmaf(w4[q].x, xv.x, a);
                a = fmaf(w4[q].y, xv.y, a);
                a = fmaf(w4[q].z, xv.z, a);
                a = fmaf(w4[q].w, xv.w, a);
            }
            mx = fmaxf(mx, a);
            sm += a;
        }
    }
    red[0][g][c] = mx;
    red[1][g][c] = sm;
    __syncthreads();
    if (tid < 32) {
        float m = red[0][0][tid], s = red[1][0][tid];
        #pragma unroll
        for (int w = 1; w < 8; w++) { m = fmaxf(m, red[0][w][tid]); s += red[1][w][tid]; }
        size_t o = ((size_t)(which*16 + b)*GSLAB + slab)*64 + tid*2;
        g_gp[o] = m; g_gp[o+1] = s;
    }
}

// ---------------- CCE apply (gate finalize folded in) ----------------
__global__ __launch_bounds__(256) void cce_apply_kernel(const float* __restrict__ w2,
                                 const float* __restrict__ ox, const float* __restrict__ oy) {
    __shared__ float sw[1024];
    __shared__ float sg[64];
    int tid = threadIdx.x;
    int b = blockIdx.y;
    for (int i = tid; i < 1024; i += 256) sw[i] = w2[i];
    if (tid < 64) {
        int which = tid >> 5, c = tid & 31;
        size_t base = ((size_t)(which*16 + b)*GSLAB)*64 + c*2;
        float m = -1e30f, s = 0.f;
        #pragma unroll
        for (int slab = 0; slab < GSLAB; slab++) {
            m = fmaxf(m, g_gp[base + slab*64]);
            s += g_gp[base + slab*64 + 1];
        }
        sg[tid] = __frcp_rn(1.f + __expf(-(m + s*(1.f/16384.f))));
    }
    __syncthreads();
    int pp = blockIdx.x * 256 + tid;
    float xv[32], yv[32];
    #pragma unroll
    for (int ci = 0; ci < 32; ci++) {
        xv[ci] = ox[((size_t)b*32 + ci)*16384 + pp];
        yv[ci] = oy[((size_t)b*32 + ci)*16384 + pp];
    }
    #pragma unroll 4
    for (int c = 0; c < 32; c++) {
        float r1 = 0.f, r2 = 0.f;
        #pragma unroll
        for (int q = 0; q < 8; q++) {
            float4 w4 = *reinterpret_cast<const float4*>(&sw[c*32 + q*4]);
            r1 = fmaf(w4.x, yv[q*4+0], r1); r2 = fmaf(w4.x, xv[q*4+0], r2);
            r1 = fmaf(w4.y, yv[q*4+1], r1); r2 = fmaf(w4.y, xv[q*4+1], r2);
            r1 = fmaf(w4.z, yv[q*4+2], r1); r2 = fmaf(w4.z, xv[q*4+2], r2);
            r1 = fmaf(w4.w, yv[q*4+3], r1); r2 = fmaf(w4.w, xv[q*4+3], r2);
        }
        size_t idx = ((size_t)b*32 + c)*16384 + pp;
        g_c2[idx] += sg[c]*r1 + sg[32+c]*r2;
    }
}

// ---------------- conv3 (32->1, 3x3) + sigmoid ----------------
__global__ void conv3_kernel(const float* __restrict__ w, const float* __restrict__ bias,
                             float* __restrict__ out) {
    __shared__ float sF[32][18][18];
    __shared__ float sw[288];
    int b = blockIdx.y;
    int tile = blockIdx.x;
    int ty0 = (tile >> 3) * 16, tx0 = (tile & 7) * 16;
    int tid = threadIdx.x;
    for (int idx = tid; idx < 32*324; idx += 256) {
        int ci = idx / 324; int rem = idx - ci*324;
        int r = rem / 18, c = rem - r*18;
        int gy = ty0 + r - 1, gx = tx0 + c - 1;
        float v = 0.f;
        if (gy >= 0 && gy < 128 && gx >= 0 && gx < 128)
            v = g_c2[(((size_t)b*32 + ci) << 14) + gy*128 + gx];
        sF[ci][r][c] = v;
    }
    for (int idx = tid; idx < 288; idx += 256) sw[idx] = w[idx];
    __syncthreads();
    int px = tid & 15, py = tid >> 4;
    float acc = bias[0];
    #pragma unroll 4
    for (int ci = 0; ci < 32; ci++)
        #pragma unroll
        for (int ky = 0; ky < 3; ky++)
            #pragma unroll
            for (int kx = 0; kx < 3; kx++)
                acc = fmaf(sw[ci*9 + ky*3 + kx], sF[ci][py + ky][px + kx], acc);
    out[((size_t)b << 14) + (ty0 + py)*128 + tx0 + px] = __frcp_rn(1.f + __expf(-acc));
}

// ---------------- launch ----------------
extern "C" void kernel_launch(void* const* d_in, const int* in_sizes, int n_in,
                              void* d_out, int out_size) {
    const float* fused_in = (const float*)d_in[0];
    const float* orig_x   = (const float*)d_in[1];
    const float* orig_y   = (const float*)d_in[2];
    const float* m_ln_g   = (const float*)d_in[3];
    const float* m_ln_b   = (const float*)d_in[4];
    const float* m_in_w   = (const float*)d_in[5];
    const float* m_conv_w = (const float*)d_in[6];
    const float* m_conv_b = (const float*)d_in[7];
    const float* m_xproj_w= (const float*)d_in[8];
    const float* m_dt_w   = (const float*)d_in[9];
    const float* m_dt_b   = (const float*)d_in[10];
    const float* m_Alog   = (const float*)d_in[11];
    const float* m_D      = (const float*)d_in[12];
    const float* m_out_w  = (const float*)d_in[13];
    const float* lnf_g    = (const float*)d_in[14];
    const float* lnf_b    = (const float*)d_in[15];
    const float* c1_w     = (const float*)d_in[16];
    const float* c1_b     = (const float*)d_in[17];
    const float* bn1_g    = (const float*)d_in[18];
    const float* bn1_b    = (const float*)d_in[19];
    const float* bn1_m    = (const float*)d_in[20];
    const float* bn1_v    = (const float*)d_in[21];
    const float* c2_w     = (const float*)d_in[22];
    const float* c2_b     = (const float*)d_in[23];
    const float* bn2_g    = (const float*)d_in[24];
    const float* bn2_b    = (const float*)d_in[25];
    const float* bn2_m    = (const float*)d_in[26];
    const float* bn2_v    = (const float*)d_in[27];
    const float* cce_w1   = (const float*)d_in[28];
    const float* cce_w2   = (const float*)d_in[29];
    const float* c3_w     = (const float*)d_in[30];
    const float* c3_b     = (const float*)d_in[31];
    float* out = (float*)d_out;

    float *p_fused, *p_h, *p_xz, *p_xm, *p_xdbl, *p_y, *p_img, *p_c1, *p_c2, *p_w1c, *p_w2c;
    cudaGetSymbolAddress((void**)&p_fused, g_fused);
    cudaGetSymbolAddress((void**)&p_h,     g_h);
    cudaGetSymbolAddress((void**)&p_xz,    g_xz);
    cudaGetSymbolAddress((void**)&p_xm,    g_xm);
    cudaGetSymbolAddress((void**)&p_xdbl,  g_xdbl);
    cudaGetSymbolAddress((void**)&p_y,     g_y);
    cudaGetSymbolAddress((void**)&p_img,   g_img);
    cudaGetSymbolAddress((void**)&p_c1,    g_c1);
    cudaGetSymbolAddress((void**)&p_c2,    g_c2);
    cudaGetSymbolAddress((void**)&p_w1c,   g_w1c);
    cudaGetSymbolAddress((void**)&p_w2c,   g_w2c);

    static int attr_set = 0;
    if (!attr_set) {
        cudaFuncSetAttribute(xproj_kernel, cudaFuncAttributeMaxDynamicSharedMemorySize, XP_SMEM);
        attr_set = 1;
    }

    // launches 1-3: weight prep + first LN; #4 = cce_gate_part (profiled slot)
    make_wc_kernel<<<32, 256>>>(c1_w, p_w1c, 64*128);
    make_wc_kernel<<<8, 256>>>(c2_w, p_w2c, 32*64);
    ln_kernel<<<2048, 256>>>(fused_in, m_ln_g, m_ln_b, p_h);
    cce_gate_part<<<dim3(GSLAB, 16, 2), 256>>>(cce_w1, orig_x, orig_y);

    // ---- 3 Mamba blocks ----
    for (int i = 0; i < 3; i++) {
        const float* src = (i == 0) ? fused_in : p_fused;
        sgemm128<<<dim3(4, 128), 256>>>(p_h, m_in_w + (size_t)i*512*128, p_xz, 512, 128);
        dwconv_silu_kernel<<<16384, 256>>>(m_conv_w + i*DI*4, m_conv_b + i*DI);
        xproj_kernel<<<512, 256, XP_SMEM>>>(p_xm, m_xproj_w + (size_t)i*24*256, p_xdbl);
        scan_pass1<<<dim3(NSEG, 16), 256>>>(m_Alog + i*DI*8, m_dt_w + i*DI*8, m_dt_b + i*DI);
        scan_pass2<<<512, 256>>>();
        scan_pass3<<<dim3(NSEG, 16), 256>>>(m_Alog + i*DI*8, m_dt_w + i*DI*8, m_dt_b + i*DI,
                                            m_D + i*DI);
        int mode = (i < 2) ? 0 : 1;
        const float* gam = (i < 2) ? (m_ln_g + (i+1)*128) : m_ln_g;
        const float* bet = (i < 2) ? (m_ln_b + (i+1)*128) : m_ln_b;
        sgemm_out_ln<<<128, 256>>>(p_y, m_out_w + (size_t)i*128*256, src,
                                   gam, bet, p_fused, p_h, mode);
    }

    // ---- final LN -> NCHW image ----
    ln_final_kernel<<<2048, 256>>>(p_fused, lnf_g, lnf_b);

    // ---- conv1: up2 + 3x3 (128->64), bn, relu ----
    conv_up2_kernel<128, 64, 32, 64, 1><<<dim3(4, 8, 16), 256>>>(
        p_img, p_c1, p_w1c, c1_b, bn1_g, bn1_b, bn1_m, bn1_v);

    // ---- conv2: up2 + 3x3 (64->32), relu, bn ----
    conv_up2_kernel<64, 32, 64, 128, 2><<<dim3(16, 4, 16), 256>>>(
        p_c1, p_c2, p_w2c, c2_b, bn2_g, bn2_b, bn2_m, bn2_v);

    // ---- CCE apply (gates finalized in-kernel from partials) ----
    cce_apply_kernel<<<dim3(64, 16), 256>>>(cce_w2, orig_x, orig_y);

    // ---- conv3 + sigmoid -> output ----
    conv3_kernel<<<dim3(64, 16), 256>>>(c3_w, c3_b, out);
}

// round 14
// speedup vs baseline: 1.0677x; 1.0677x over previous
#include <cuda_runtime.h>
#include <math.h>

// ---------------- sizes ----------------
#define B_    16
#define L_    1024
#define DM    128
#define DI    256
#define MTOT  (B_*L_)      // 16384 rows
#define NSEG  64
#define LSEG  16
#define GSLAB 32

// ---------------- scratch (device globals; no allocation) ----------------
__device__ float g_fused[MTOT*DM];
__device__ float g_h    [MTOT*DM];
__device__ float g_xz   [MTOT*2*DI];      // [0,256)=xm_pre, [256,512)=z
__device__ float g_xm   [MTOT*DI];
__device__ float g_xdbl [MTOT*24];
__device__ float2 g_duw [MTOT*DI];        // per (m,d): {dt, w1=exp(-dt)} cached by pass1
__device__ float g_y    [MTOT*DI];
__device__ float g_agg  [B_*DI*NSEG*16];  // [b][d][seg][P8|H8]
__device__ float g_img  [B_*DM*1024];     // NCHW (16,128,32,32)
__device__ float g_c1   [B_*64*64*64];
__device__ float g_c2   [B_*32*128*128];
__device__ float g_w1c  [64*128*16];
__device__ float g_w2c  [32*64*16];
__device__ float g_gp   [2*16*GSLAB*64];

// ---------------- LayerNorm (warp per row of 128) ----------------
__global__ void ln_kernel(const float* __restrict__ x, const float* __restrict__ gam,
                          const float* __restrict__ bet, float* __restrict__ out) {
    int gw   = (blockIdx.x * blockDim.x + threadIdx.x) >> 5;
    int lane = threadIdx.x & 31;
    float4 v = *reinterpret_cast<const float4*>(x + (size_t)gw*128 + lane*4);
    float s  = v.x + v.y + v.z + v.w;
    float ss = v.x*v.x + v.y*v.y + v.z*v.z + v.w*v.w;
    #pragma unroll
    for (int o = 16; o; o >>= 1) {
        s  += __shfl_xor_sync(0xffffffffu, s,  o);
        ss += __shfl_xor_sync(0xffffffffu, ss, o);
    }
    float mean = s * (1.f/128.f);
    float var  = ss * (1.f/128.f) - mean*mean;
    float r    = rsqrtf(var + 1e-5f);
    float4 g4  = *reinterpret_cast<const float4*>(gam + lane*4);
    float4 b4  = *reinterpret_cast<const float4*>(bet + lane*4);
    float4 o4;
    o4.x = (v.x-mean)*r*g4.x + b4.x;
    o4.y = (v.y-mean)*r*g4.y + b4.y;
    o4.z = (v.z-mean)*r*g4.z + b4.z;
    o4.w = (v.w-mean)*r*g4.w + b4.w;
    *reinterpret_cast<float4*>(out + (size_t)gw*128 + lane*4) = o4;
}

__global__ void ln_final_kernel(const float* __restrict__ x, const float* __restrict__ gam,
                                const float* __restrict__ bet) {
    int gw   = (blockIdx.x * blockDim.x + threadIdx.x) >> 5;
    int lane = threadIdx.x & 31;
    float4 v = *reinterpret_cast<const float4*>(x + (size_t)gw*128 + lane*4);
    float s  = v.x + v.y + v.z + v.w;
    float ss = v.x*v.x + v.y*v.y + v.z*v.z + v.w*v.w;
    #pragma unroll
    for (int o = 16; o; o >>= 1) {
        s  += __shfl_xor_sync(0xffffffffu, s,  o);
        ss += __shfl_xor_sync(0xffffffffu, ss, o);
    }
    float mean = s * (1.f/128.f);
    float var  = ss * (1.f/128.f) - mean*mean;
    float r    = rsqrtf(var + 1e-5f);
    float4 g4  = *reinterpret_cast<const float4*>(gam + lane*4);
    float4 b4  = *reinterpret_cast<const float4*>(bet + lane*4);
    int b = gw >> 10, l = gw & 1023;
    size_t base = ((size_t)b*128 + lane*4)*1024 + l;
    g_img[base + 0*1024] = (v.x-mean)*r*g4.x + b4.x;
    g_img[base + 1*1024] = (v.y-mean)*r*g4.y + b4.y;
    g_img[base + 2*1024] = (v.z-mean)*r*g4.z + b4.z;
    g_img[base + 3*1024] = (v.w-mean)*r*g4.w + b4.w;
}

// ---------------- SGEMM 128x128x16: C[M,N] = A[M,K] @ W[N,K]^T (in_proj) ----------------
__global__ __launch_bounds__(256, 2) void sgemm128(const float* __restrict__ A,
        const float* __restrict__ W, float* __restrict__ C, int N, int K) {
    __shared__ float As[16][128];
    __shared__ float Bs[16][128];
    const int tid = threadIdx.x;
    const int m0 = blockIdx.y * 128, n0 = blockIdx.x * 128;
    const int tx = tid & 15, ty = tid >> 4;
    const int lr = tid >> 1, lc = (tid & 1) * 8;
    float acc[8][8];
    #pragma unroll
    for (int i = 0; i < 8; i++)
        #pragma unroll
        for (int j = 0; j < 8; j++) acc[i][j] = 0.f;

    const float* Ap = A + (size_t)(m0 + lr)*K + lc;
    const float* Wp = W + (size_t)(n0 + lr)*K + lc;

    for (int k0 = 0; k0 < K; k0 += 16) {
        float4 a0 = *reinterpret_cast<const float4*>(Ap + k0);
        float4 a1 = *reinterpret_cast<const float4*>(Ap + k0 + 4);
        float4 b0 = *reinterpret_cast<const float4*>(Wp + k0);
        float4 b1 = *reinterpret_cast<const float4*>(Wp + k0 + 4);
        __syncthreads();
        As[lc+0][lr]=a0.x; As[lc+1][lr]=a0.y; As[lc+2][lr]=a0.z; As[lc+3][lr]=a0.w;
        As[lc+4][lr]=a1.x; As[lc+5][lr]=a1.y; As[lc+6][lr]=a1.z; As[lc+7][lr]=a1.w;
        Bs[lc+0][lr]=b0.x; Bs[lc+1][lr]=b0.y; Bs[lc+2][lr]=b0.z; Bs[lc+3][lr]=b0.w;
        Bs[lc+4][lr]=b1.x; Bs[lc+5][lr]=b1.y; Bs[lc+6][lr]=b1.z; Bs[lc+7][lr]=b1.w;
        __syncthreads();
        #pragma unroll
        for (int k = 0; k < 16; k++) {
            float4 af0 = *reinterpret_cast<const float4*>(&As[k][ty*8]);
            float4 af1 = *reinterpret_cast<const float4*>(&As[k][ty*8+4]);
            float4 bf0 = *reinterpret_cast<const float4*>(&Bs[k][tx*8]);
            float4 bf1 = *reinterpret_cast<const float4*>(&Bs[k][tx*8+4]);
            float av[8] = {af0.x,af0.y,af0.z,af0.w,af1.x,af1.y,af1.z,af1.w};
            float bv[8] = {bf0.x,bf0.y,bf0.z,bf0.w,bf1.x,bf1.y,bf1.z,bf1.w};
            #pragma unroll
            for (int i = 0; i < 8; i++)
                #pragma unroll
                for (int j = 0; j < 8; j++)
                    acc[i][j] = fmaf(av[i], bv[j], acc[i][j]);
        }
    }
    #pragma unroll
    for (int i = 0; i < 8; i++) {
        size_t row = (size_t)(m0 + ty*8 + i)*N + n0 + tx*8;
        *reinterpret_cast<float4*>(C + row)     = make_float4(acc[i][0], acc[i][1], acc[i][2], acc[i][3]);
        *reinterpret_cast<float4*>(C + row + 4) = make_float4(acc[i][4], acc[i][5], acc[i][6], acc[i][7]);
    }
}

// ---------------- out_proj + residual + (next) LayerNorm fused ----------------
__global__ __launch_bounds__(256, 2) void sgemm_out_ln(const float* __restrict__ A,
        const float* __restrict__ W, const float* __restrict__ skip,
        const float* __restrict__ gam, const float* __restrict__ bet,
        float* __restrict__ fused_out, float* __restrict__ h_out, int mode) {
    const int K = 256, N = 128;
    __shared__ float As[16][128];
    __shared__ float Bs[16][128];
    const int tid = threadIdx.x;
    const int m0 = blockIdx.x * 128;
    const int tx = tid & 15, ty = tid >> 4;
    const int lr = tid >> 1, lc = (tid & 1) * 8;
    float acc[8][8];
    #pragma unroll
    for (int i = 0; i < 8; i++)
        #pragma unroll
        for (int j = 0; j < 8; j++) acc[i][j] = 0.f;

    const float* Ap = A + (size_t)(m0 + lr)*K + lc;
    const float* Wp = W + (size_t)lr*K + lc;

    for (int k0 = 0; k0 < K; k0 += 16) {
        float4 a0 = *reinterpret_cast<const float4*>(Ap + k0);
        float4 a1 = *reinterpret_cast<const float4*>(Ap + k0 + 4);
        float4 b0 = *reinterpret_cast<const float4*>(Wp + k0);
        float4 b1 = *reinterpret_cast<const float4*>(Wp + k0 + 4);
        __syncthreads();
        As[lc+0][lr]=a0.x; As[lc+1][lr]=a0.y; As[lc+2][lr]=a0.z; As[lc+3][lr]=a0.w;
        As[lc+4][lr]=a1.x; As[lc+5][lr]=a1.y; As[lc+6][lr]=a1.z; As[lc+7][lr]=a1.w;
        Bs[lc+0][lr]=b0.x; Bs[lc+1][lr]=b0.y; Bs[lc+2][lr]=b0.z; Bs[lc+3][lr]=b0.w;
        Bs[lc+4][lr]=b1.x; Bs[lc+5][lr]=b1.y; Bs[lc+6][lr]=b1.z; Bs[lc+7][lr]=b1.w;
        __syncthreads();
        #pragma unroll
        for (int k = 0; k < 16; k++) {
            float4 af0 = *reinterpret_cast<const float4*>(&As[k][ty*8]);
            float4 af1 = *reinterpret_cast<const float4*>(&As[k][ty*8+4]);
            float4 bf0 = *reinterpret_cast<const float4*>(&Bs[k][tx*8]);
            float4 bf1 = *reinterpret_cast<const float4*>(&Bs[k][tx*8+4]);
            float av[8] = {af0.x,af0.y,af0.z,af0.w,af1.x,af1.y,af1.z,af1.w};
            float bv[8] = {bf0.x,bf0.y,bf0.z,bf0.w,bf1.x,bf1.y,bf1.z,bf1.w};
            #pragma unroll
            for (int i = 0; i < 8; i++)
                #pragma unroll
                for (int j = 0; j < 8; j++)
                    acc[i][j] = fmaf(av[i], bv[j], acc[i][j]);
        }
    }
    float4 g0 = make_float4(0,0,0,0), g1 = g0, be0 = g0, be1 = g0;
    if (mode == 0) {
        g0  = *reinterpret_cast<const float4*>(gam + tx*8);
        g1  = *reinterpret_cast<const float4*>(gam + tx*8 + 4);
        be0 = *reinterpret_cast<const float4*>(bet + tx*8);
        be1 = *reinterpret_cast<const float4*>(bet + tx*8 + 4);
    }
    #pragma unroll
    for (int i = 0; i < 8; i++) {
        size_t row = (size_t)(m0 + ty*8 + i)*N + tx*8;
        float4 s0 = *reinterpret_cast<const float4*>(skip + row);
        float4 s1 = *reinterpret_cast<const float4*>(skip + row + 4);
        float v[8];
        v[0]=acc[i][0]+s0.x; v[1]=acc[i][1]+s0.y; v[2]=acc[i][2]+s0.z; v[3]=acc[i][3]+s0.w;
        v[4]=acc[i][4]+s1.x; v[5]=acc[i][5]+s1.y; v[6]=acc[i][6]+s1.z; v[7]=acc[i][7]+s1.w;
        *reinterpret_cast<float4*>(fused_out + row)     = make_float4(v[0],v[1],v[2],v[3]);
        *reinterpret_cast<float4*>(fused_out + row + 4) = make_float4(v[4],v[5],v[6],v[7]);
        if (mode == 0) {
            float s = 0.f, ss = 0.f;
            #pragma unroll
            for (int j = 0; j < 8; j++) { s += v[j]; ss += v[j]*v[j]; }
            #pragma unroll
            for (int o = 1; o < 16; o <<= 1) {
                s  += __shfl_xor_sync(0xffffffffu, s,  o);
                ss += __shfl_xor_sync(0xffffffffu, ss, o);
            }
            float mean = s * (1.f/128.f);
            float var  = ss * (1.f/128.f) - mean*mean;
            float r    = rsqrtf(var + 1e-5f);
            float h[8];
            h[0]=(v[0]-mean)*r*g0.x+be0.x; h[1]=(v[1]-mean)*r*g0.y+be0.y;
            h[2]=(v[2]-mean)*r*g0.z+be0.z; h[3]=(v[3]-mean)*r*g0.w+be0.w;
            h[4]=(v[4]-mean)*r*g1.x+be1.x; h[5]=(v[5]-mean)*r*g1.y+be1.y;
            h[6]=(v[6]-mean)*r*g1.z+be1.z; h[7]=(v[7]-mean)*r*g1.w+be1.w;
            *reinterpret_cast<float4*>(h_out + row)     = make_float4(h[0],h[1],h[2],h[3]);
            *reinterpret_cast<float4*>(h_out + row + 4) = make_float4(h[4],h[5],h[6],h[7]);
        }
    }
}

// ---------------- small-N GEMM (xproj, N=24, K=256) ----------------
__global__ void gemm_tn_kernel(const float* __restrict__ A, const float* __restrict__ W,
                               float* __restrict__ C, int N, int K) {
    __shared__ float As[16][68];
    __shared__ float Bs[16][68];
    int tid = threadIdx.x;
    int m0 = blockIdx.y * 64, n0 = blockIdx.x * 64;
    int tx = tid & 15, ty = tid >> 4;
    int lm = tid >> 2, lk = (tid & 3) * 4;
    float acc[4][4];
    #pragma unroll
    for (int i = 0; i < 4; i++)
        #pragma unroll
        for (int j = 0; j < 4; j++) acc[i][j] = 0.f;

    const float* Ap = A + (size_t)(m0 + lm)*K + lk;
    bool wok = (n0 + lm) < N;
    const float* Wp = W + (size_t)(n0 + lm)*K + lk;

    for (int k0 = 0; k0 < K; k0 += 16) {
        float4 a4 = *reinterpret_cast<const float4*>(Ap + k0);
        float4 w4 = wok ? *reinterpret_cast<const float4*>(Wp + k0)
                        : make_float4(0.f,0.f,0.f,0.f);
        As[lk+0][lm] = a4.x; As[lk+1][lm] = a4.y; As[lk+2][lm] = a4.z; As[lk+3][lm] = a4.w;
        Bs[lk+0][lm] = w4.x; Bs[lk+1][lm] = w4.y; Bs[lk+2][lm] = w4.z; Bs[lk+3][lm] = w4.w;
        __syncthreads();
        #pragma unroll
        for (int k = 0; k < 16; k++) {
            float4 av = *reinterpret_cast<const float4*>(&As[k][ty*4]);
            float4 bv = *reinterpret_cast<const float4*>(&Bs[k][tx*4]);
            float aa[4] = {av.x, av.y, av.z, av.w};
            float bb[4] = {bv.x, bv.y, bv.z, bv.w};
            #pragma unroll
            for (int i = 0; i < 4; i++)
                #pragma unroll
                for (int j = 0; j < 4; j++)
                    acc[i][j] = fmaf(aa[i], bb[j], acc[i][j]);
        }
        __syncthreads();
    }
    #pragma unroll
    for (int i = 0; i < 4; i++) {
        int m = m0 + ty*4 + i;
        #pragma unroll
        for (int j = 0; j < 4; j++) {
            int n = n0 + tx*4 + j;
            if (n < N) C[(size_t)m*N + n] = acc[i][j];
        }
    }
}

// ---------------- depthwise causal conv1d (k=4) + bias + SiLU ----------------
__global__ void dwconv_silu_kernel(const float* __restrict__ w, const float* __restrict__ bias) {
    int idx = blockIdx.x * blockDim.x + threadIdx.x;
    int d = idx & (DI-1);
    int m = idx >> 8;
    int l = m & 1023;
    float acc = bias[d];
    #pragma unroll
    for (int k = 0; k < 4; k++) {
        int ll = l + k - 3;
        if (ll >= 0) acc = fmaf(w[d*4 + k], g_xz[(size_t)(m + k - 3)*512 + d], acc);
    }
    g_xm[idx] = acc * __frcp_rn(1.f + __expf(-acc));
}

// ---------------- dt/w1 helper ----------------
__device__ __forceinline__ void dt_w1(float acc, float& dt, float& w1) {
    float e = __expf(acc);
    w1 = __frcp_rn(1.f + e);
    dt = (acc > 20.f) ? acc : __logf(1.f + e);
}

// ---------------- scan pass1: aggregates + (dt,w1) cache ----------------
__global__ __launch_bounds__(256) void scan_pass1(const float* __restrict__ Alog,
        const float* __restrict__ dtw, const float* __restrict__ dtb) {
    __shared__ float sA[2048], sW[2048], sB[256];
    int tid = threadIdx.x;
    for (int i = tid; i < 2048; i += 256) { sA[i] = -expf(Alog[i]); sW[i] = dtw[i]; }
    sB[tid] = dtb[tid];
    __syncthreads();
    int d = tid, seg = blockIdx.x, b = blockIdx.y;
    float A[8], wj[8];
    bool fast = true;
    #pragma unroll
    for (int n = 0; n < 8; n++) {
        A[n] = sA[d*8+n]; wj[n] = sW[d*8+n];
        fast = fast && (fabsf(A[n] + (float)(n+1)) < 1e-3f*(float)(n+1));
    }
    float bt = sB[d];
    float P[8], H[8];
    #pragma unroll
    for (int n = 0; n < 8; n++) { P[n] = 1.f; H[n] = 0.f; }
    int m0 = (b << 10) + (seg << 4);
    #pragma unroll 2
    for (int l = 0; l < LSEG; l++) {
        int m = m0 + l;
        float u = g_xm[(size_t)m*256 + d];
        const float* r = g_xdbl + (size_t)m*24;
        float acc = bt;
        #pragma unroll
        for (int j = 0; j < 8; j++) acc = fmaf(__ldg(r + j), wj[j], acc);
        float dt, w1;
        dt_w1(acc, dt, w1);
        g_duw[(size_t)m*256 + d] = make_float2(dt, w1);
        float p[8];
        if (fast) {
            p[0] = w1;
            #pragma unroll
            for (int n = 1; n < 8; n++) p[n] = p[n-1]*w1;
        } else {
            #pragma unroll
            for (int n = 0; n < 8; n++) p[n] = __expf(dt*A[n]);
        }
        float du = dt * u;
        float4 B0 = *reinterpret_cast<const float4*>(r + 8);
        float4 B1 = *reinterpret_cast<const float4*>(r + 12);
        float Bv[8] = {B0.x,B0.y,B0.z,B0.w,B1.x,B1.y,B1.z,B1.w};
        #pragma unroll
        for (int n = 0; n < 8; n++) {
            P[n] *= p[n];
            H[n] = fmaf(p[n], H[n], du * Bv[n]);
        }
    }
    size_t base = ((size_t)((b*256 + d))*NSEG + seg) * 16;
    float4* o = reinterpret_cast<float4*>(g_agg + base);
    o[0] = make_float4(P[0],P[1],P[2],P[3]);
    o[1] = make_float4(P[4],P[5],P[6],P[7]);
    o[2] = make_float4(H[0],H[1],H[2],H[3]);
    o[3] = make_float4(H[4],H[5],H[6],H[7]);
}

// ---------------- scan pass2: PARALLEL warp-scan (R10 winner, NSEG=64) ----------------
__global__ __launch_bounds__(256) void scan_pass2() {
    int wid = threadIdx.x >> 5, lane = threadIdx.x & 31;
    size_t pair = (size_t)blockIdx.x * 8 + wid;
    float4* base = reinterpret_cast<float4*>(g_agg + pair * (NSEG*16));
    float4 a0 = base[lane*8 + 0], a1 = base[lane*8 + 1];
    float4 a2 = base[lane*8 + 2], a3 = base[lane*8 + 3];
    float4 b0 = base[lane*8 + 4], b1 = base[lane*8 + 5];
    float4 b2 = base[lane*8 + 6], b3 = base[lane*8 + 7];
    float Pa[8] = {a0.x,a0.y,a0.z,a0.w,a1.x,a1.y,a1.z,a1.w};
    float Ha[8] = {a2.x,a2.y,a2.z,a2.w,a3.x,a3.y,a3.z,a3.w};
    float P[8], H[8];
    P[0]=Pa[0]*b0.x; H[0]=fmaf(b0.x,Ha[0],b2.x);
    P[1]=Pa[1]*b0.y; H[1]=fmaf(b0.y,Ha[1],b2.y);
    P[2]=Pa[2]*b0.z; H[2]=fmaf(b0.z,Ha[2],b2.z);
    P[3]=Pa[3]*b0.w; H[3]=fmaf(b0.w,Ha[3],b2.w);
    P[4]=Pa[4]*b1.x; H[4]=fmaf(b1.x,Ha[4],b3.x);
    P[5]=Pa[5]*b1.y; H[5]=fmaf(b1.y,Ha[5],b3.y);
    P[6]=Pa[6]*b1.z; H[6]=fmaf(b1.z,Ha[6],b3.z);
    P[7]=Pa[7]*b1.w; H[7]=fmaf(b1.w,Ha[7],b3.w);
    #pragma unroll
    for (int dd = 1; dd < 32; dd <<= 1) {
        #pragma unroll
        for (int n = 0; n < 8; n++) {
            float po = __shfl_up_sync(0xffffffffu, P[n], dd);
            float ho = __shfl_up_sync(0xffffffffu, H[n], dd);
            if (lane >= dd) { H[n] = fmaf(P[n], ho, H[n]); P[n] *= po; }
        }
    }
    float hp[8];
    #pragma unroll
    for (int n = 0; n < 8; n++) {
        float h = __shfl_up_sync(0xffffffffu, H[n], 1);
        hp[n] = (lane == 0) ? 0.f : h;
    }
    base[lane*8 + 2] = make_float4(hp[0],hp[1],hp[2],hp[3]);
    base[lane*8 + 3] = make_float4(hp[4],hp[5],hp[6],hp[7]);
    float hq[8];
    #pragma unroll
    for (int n = 0; n < 8; n++) hq[n] = fmaf(Pa[n], hp[n], Ha[n]);
    base[lane*8 + 6] = make_float4(hq[0],hq[1],hq[2],hq[3]);
    base[lane*8 + 7] = make_float4(hq[4],hq[5],hq[6],hq[7]);
}

// ---------------- scan pass3: uses cached (dt,w1); emit y*silu(z) ----------------
__global__ __launch_bounds__(256) void scan_pass3(const float* __restrict__ Alog,
        const float* __restrict__ Dp) {
    __shared__ float sA[2048], sD[256];
    int tid = threadIdx.x;
    for (int i = tid; i < 2048; i += 256) sA[i] = -expf(Alog[i]);
    sD[tid] = Dp[tid];
    __syncthreads();
    int d = tid, seg = blockIdx.x, b = blockIdx.y;
    float A[8];
    bool fast = true;
    #pragma unroll
    for (int n = 0; n < 8; n++) {
        A[n] = sA[d*8+n];
        fast = fast && (fabsf(A[n] + (float)(n+1)) < 1e-3f*(float)(n+1));
    }
    float Dd = sD[d];
    size_t base = ((size_t)((b*256 + d))*NSEG + seg) * 16;
    float4 h0 = *reinterpret_cast<const float4*>(g_agg + base + 8);
    float4 h1 = *reinterpret_cast<const float4*>(g_agg + base + 12);
    float h[8] = {h0.x,h0.y,h0.z,h0.w,h1.x,h1.y,h1.z,h1.w};
    int m0 = (b << 10) + (seg << 4);
    #pragma unroll 2
    for (int l = 0; l < LSEG; l++) {
        int m = m0 + l;
        float u = g_xm[(size_t)m*256 + d];
        float2 dw = g_duw[(size_t)m*256 + d];
        float dt = dw.x, w1 = dw.y;
        const float* r = g_xdbl + (size_t)m*24;
        float p[8];
        if (fast) {
            p[0] = w1;
            #pragma unroll
            for (int n = 1; n < 8; n++) p[n] = p[n-1]*w1;
        } else {
            #pragma unroll
            for (int n = 0; n < 8; n++) p[n] = __expf(dt*A[n]);
        }
        float du = dt * u;
        float4 B0 = *reinterpret_cast<const float4*>(r + 8);
        float4 B1 = *reinterpret_cast<const float4*>(r + 12);
        float4 C0 = *reinterpret_cast<const float4*>(r + 16);
        float4 C1 = *reinterpret_cast<const float4*>(r + 20);
        float Bv[8] = {B0.x,B0.y,B0.z,B0.w,B1.x,B1.y,B1.z,B1.w};
        float Cv[8] = {C0.x,C0.y,C0.z,C0.w,C1.x,C1.y,C1.z,C1.w};
        float ys0 = 0.f, ys1 = 0.f;
        #pragma unroll
        for (int n = 0; n < 8; n++) {
            h[n] = fmaf(p[n], h[n], du * Bv[n]);
            if (n & 1) ys1 = fmaf(h[n], Cv[n], ys1);
            else       ys0 = fmaf(h[n], Cv[n], ys0);
        }
        float z  = g_xz[(size_t)m*512 + 256 + d];
        float sz = z * __frcp_rn(1.f + __expf(-z));
        g_y[(size_t)m*256 + d] = (ys0 + ys1 + u*Dd) * sz;
    }
}

// ---------------- combined 2x2 weights ----------------
__global__ void make_wc_kernel(const float* __restrict__ w, float* __restrict__ wc, int total) {
    int i = blockIdx.x * 256 + threadIdx.x;
    if (i >= total) return;
    const float* ws = w + (size_t)i*9;
    float t[3][4];
    #pragma unroll
    for (int ky = 0; ky < 3; ky++) {
        float w0 = ws[ky*3+0], w1 = ws[ky*3+1], w2 = ws[ky*3+2];
        t[ky][0] = w0;
        t[ky][1] = w1 + w2;
        t[ky][2] = w0 + w1;
        t[ky][3] = w2;
    }
    float* o = wc + (size_t)i*16;
    #pragma unroll
    for (int bk = 0; bk < 2; bk++) {
        o[(0*2+bk)*4 + 0*2 + 0] = t[0][bk*2+0];
        o[(0*2+bk)*4 + 0*2 + 1] = t[0][bk*2+1];
        o[(0*2+bk)*4 + 1*2 + 0] = t[1][bk*2+0] + t[2][bk*2+0];
        o[(0*2+bk)*4 + 1*2 + 1] = t[1][bk*2+1] + t[2][bk*2+1];
        o[(1*2+bk)*4 + 0*2 + 0] = t[0][bk*2+0] + t[1][bk*2+0];
        o[(1*2+bk)*4 + 0*2 + 1] = t[0][bk*2+1] + t[1][bk*2+1];
        o[(1*2+bk)*4 + 1*2 + 0] = t[2][bk*2+0];
        o[(1*2+bk)*4 + 1*2 + 1] = t[2][bk*2+1];
    }
}

// ---------------- up2+3x3 conv via 2x2 combined weights (R2 winner) ----------------
template<int CI, int CO, int SRCD, int OUTD, int MODE>
__global__ __launch_bounds__(256) void conv_up2_kernel(
        const float* __restrict__ in, float* __restrict__ out,
        const float* __restrict__ Wc, const float* __restrict__ bias,
        const float* __restrict__ bng, const float* __restrict__ bnb,
        const float* __restrict__ bnm, const float* __restrict__ bnv) {
    __shared__ float s_x[16][18][18];
    __shared__ float s_w[2048];
    const int tid = threadIdx.x;
    const int b   = blockIdx.z;
    const int cog = blockIdx.y;
    const int ntx = OUTD / 32;
    const int tyi = blockIdx.x / ntx, txi = blockIdx.x % ntx;
    const int oy0 = tyi*32, ox0 = txi*32;
    const int sy0 = oy0/2 - 1, sx0 = ox0/2 - 1;
    const int px = tid & 15, py = tid >> 4;
    const int pa = py & 1, pb = px & 1;
    const int p  = pa*2 + pb;

    int rbase[2], cbase[2];
    #pragma unroll
    for (int i = 0; i < 2; i++) {
        rbase[i] = ((py + 16*i) >> 1) + pa;
        cbase[i] = ((px + 16*i) >> 1) + pb;
    }

    float acc[8][4];
    #pragma unroll
    for (int c = 0; c < 8; c++)
        #pragma unroll
        for (int q = 0; q < 4; q++) acc[c][q] = 0.f;

    for (int cc = 0; cc < CI; cc += 16) {
        for (int idx = tid; idx < 16*324; idx += 256) {
            int ci = idx / 324; int rem = idx - ci*324;
            int r = rem / 18, c = rem - r*18;
            int sy = sy0 + r, sxp = sx0 + c;
            float v = 0.f;
            if (sy >= 0 && sy < SRCD && sxp >= 0 && sxp < SRCD)
                v = in[(((size_t)b*CI + cc + ci)*SRCD + sy)*SRCD + sxp];
            s_x[ci][r][c] = v;
        }
        for (int i = tid; i < 2048; i += 256) {
            int ci = i >> 7, rem = i & 127;
            int pp = rem >> 5, co = (rem >> 2) & 7, jk = i & 3;
            s_w[i] = Wc[((size_t)(cog*8 + co)*CI + cc + ci)*16 + pp*4 + jk];
        }
        __syncthreads();
        #pragma unroll 2
        for (int ci = 0; ci < 16; ci++) {
            float4 w4[8];
            #pragma unroll
            for (int co = 0; co < 8; co++)
                w4[co] = *reinterpret_cast<const float4*>(&s_w[((ci*4 + p)*8 + co)*4]);
            #pragma unroll
            for (int iq = 0; iq < 2; iq++)
                #pragma unroll
                for (int jq = 0; jq < 2; jq++) {
                    int q = iq*2 + jq;
                    float x00 = s_x[ci][rbase[iq]+0][cbase[jq]+0];
                    float x01 = s_x[ci][rbase[iq]+0][cbase[jq]+1];
                    float x10 = s_x[ci][rbase[iq]+1][cbase[jq]+0];
                    float x11 = s_x[ci][rbase[iq]+1][cbase[jq]+1];
                    #pragma unroll
                    for (int co = 0; co < 8; co++) {
                        float a = acc[co][q];
                        a = fmaf(w4[co].x, x00, a);
                        a = fmaf(w4[co].y, x01, a);
                        a = fmaf(w4[co].z, x10, a);
                        a = fmaf(w4[co].w, x11, a);
                        acc[co][q] = a;
                    }
                }
        }
        __syncthreads();
    }
    #pragma unroll
    for (int co = 0; co < 8; co++) {
        int c = cog*8 + co;
        float sc = bng[c] * rsqrtf(bnv[c] + 1e-5f);
        float sh2 = bnb[c] - bnm[c]*sc;
        float bsv = bias[c];
        #pragma unroll
        for (int q = 0; q < 4; q++) {
            int i = q >> 1, j = q & 1;
            int oy = oy0 + py + 16*i, ox = ox0 + px + 16*j;
            float v = acc[co][q] + bsv;
            v = (MODE == 1) ? fmaxf(v*sc + sh2, 0.f) : (fmaxf(v, 0.f)*sc + sh2);
            out[(((size_t)b*CO + c)*OUTD + oy)*OUTD + ox] = v;
        }
    }
}

// ---------------- CCE gate partials (R11/R12 winner) ----------------
__global__ __launch_bounds__(256) void cce_gate_part(const float* __restrict__ w1,
        const float* __restrict__ ox, const float* __restrict__ oy) {
    __shared__ float sw[1024];
    __shared__ float sx[64*36];
    __shared__ float red[2][8][32];
    int tid = threadIdx.x;
    for (int i = tid; i < 1024; i += 256) sw[i] = w1[i];
    __syncthreads();
    int which = blockIdx.z, b = blockIdx.y, slab = blockIdx.x;
    const float* base = (which ? oy : ox) + (size_t)b*32*16384;
    int c = tid & 31, g = tid >> 5;
    float4 w4[8];
    #pragma unroll
    for (int q = 0; q < 8; q++)
        w4[q] = *reinterpret_cast<const float4*>(&sw[c*32 + q*4]);
    float mx = -1e30f, sm = 0.f;
    int p0 = slab * (16384/GSLAB);
    #pragma unroll 1
    for (int it = 0; it < (16384/GSLAB)/64; it++) {
        int pt = p0 + it*64;
        __syncthreads();
        for (int i = tid; i < 512; i += 256) {
            int ci = i >> 4, p4 = (i & 15) * 4;
            float4 v = *reinterpret_cast<const float4*>(base + (size_t)ci*16384 + pt + p4);
            sx[(p4+0)*36 + ci] = v.x;
            sx[(p4+1)*36 + ci] = v.y;
            sx[(p4+2)*36 + ci] = v.z;
            sx[(p4+3)*36 + ci] = v.w;
        }
        __syncthreads();
        #pragma unroll
        for (int pp = 0; pp < 8; pp++) {
            const float* xr = &sx[(g*8 + pp)*36];
            float a = 0.f;
            #pragma unroll
            for (int q = 0; q < 8; q++) {
                float4 xv = *reinterpret_cast<const float4*>(xr + q*4);
                a = fmaf(w4[q].x, xv.x, a);
                a = fmaf(w4[q].y, xv.y, a);
                a = fmaf(w4[q].z, xv.z, a);
                a = fmaf(w4[q].w, xv.w, a);
            }
            mx = fmaxf(mx, a);
            sm += a;
        }
    }
    red[0][g][c] = mx;
    red[1][g][c] = sm;
    __syncthreads();
    if (tid < 32) {
        float m = red[0][0][tid], s = red[1][0][tid];
        #pragma unroll
        for (int w = 1; w < 8; w++) { m = fmaxf(m, red[0][w][tid]); s += red[1][w][tid]; }
        size_t o = ((size_t)(which*16 + b)*GSLAB + slab)*64 + tid*2;
        g_gp[o] = m; g_gp[o+1] = s;
    }
}

// ---------------- CCE apply (gate finalize folded in) ----------------
__global__ __launch_bounds__(256) void cce_apply_kernel(const float* __restrict__ w2,
                                 const float* __restrict__ ox, const float* __restrict__ oy) {
    __shared__ float sw[1024];
    __shared__ float sg[64];
    int tid = threadIdx.x;
    int b = blockIdx.y;
    for (int i = tid; i < 1024; i += 256) sw[i] = w2[i];
    if (tid < 64) {
        int which = tid >> 5, c = tid & 31;
        size_t base = ((size_t)(which*16 + b)*GSLAB)*64 + c*2;
        float m = -1e30f, s = 0.f;
        #pragma unroll
        for (int slab = 0; slab < GSLAB; slab++) {
            m = fmaxf(m, g_gp[base + slab*64]);
            s += g_gp[base + slab*64 + 1];
        }
        sg[tid] = __frcp_rn(1.f + __expf(-(m + s*(1.f/16384.f))));
    }
    __syncthreads();
    int pp = blockIdx.x * 256 + tid;
    float xv[32], yv[32];
    #pragma unroll
    for (int ci = 0; ci < 32; ci++) {
        xv[ci] = ox[((size_t)b*32 + ci)*16384 + pp];
        yv[ci] = oy[((size_t)b*32 + ci)*16384 + pp];
    }
    #pragma unroll 4
    for (int c = 0; c < 32; c++) {
        float r1 = 0.f, r2 = 0.f;
        #pragma unroll
        for (int q = 0; q < 8; q++) {
            float4 w4 = *reinterpret_cast<const float4*>(&sw[c*32 + q*4]);
            r1 = fmaf(w4.x, yv[q*4+0], r1); r2 = fmaf(w4.x, xv[q*4+0], r2);
            r1 = fmaf(w4.y, yv[q*4+1], r1); r2 = fmaf(w4.y, xv[q*4+1], r2);
            r1 = fmaf(w4.z, yv[q*4+2], r1); r2 = fmaf(w4.z, xv[q*4+2], r2);
            r1 = fmaf(w4.w, yv[q*4+3], r1); r2 = fmaf(w4.w, xv[q*4+3], r2);
        }
        size_t idx = ((size_t)b*32 + c)*16384 + pp;
        g_c2[idx] += sg[c]*r1 + sg[32+c]*r2;
    }
}

// ---------------- conv3 (32->1, 3x3) + sigmoid ----------------
__global__ void conv3_kernel(const float* __restrict__ w, const float* __restrict__ bias,
                             float* __restrict__ out) {
    __shared__ float sF[32][18][18];
    __shared__ float sw[288];
    int b = blockIdx.y;
    int tile = blockIdx.x;
    int ty0 = (tile >> 3) * 16, tx0 = (tile & 7) * 16;
    int tid = threadIdx.x;
    for (int idx = tid; idx < 32*324; idx += 256) {
        int ci = idx / 324; int rem = idx - ci*324;
        int r = rem / 18, c = rem - r*18;
        int gy = ty0 + r - 1, gx = tx0 + c - 1;
        float v = 0.f;
        if (gy >= 0 && gy < 128 && gx >= 0 && gx < 128)
            v = g_c2[(((size_t)b*32 + ci) << 14) + gy*128 + gx];
        sF[ci][r][c] = v;
    }
    for (int idx = tid; idx < 288; idx += 256) sw[idx] = w[idx];
    __syncthreads();
    int px = tid & 15, py = tid >> 4;
    float acc = bias[0];
    #pragma unroll 4
    for (int ci = 0; ci < 32; ci++)
        #pragma unroll
        for (int ky = 0; ky < 3; ky++)
            #pragma unroll
            for (int kx = 0; kx < 3; kx++)
                acc = fmaf(sw[ci*9 + ky*3 + kx], sF[ci][py + ky][px + kx], acc);
    out[((size_t)b << 14) + (ty0 + py)*128 + tx0 + px] = __frcp_rn(1.f + __expf(-acc));
}

// ---------------- launch ----------------
extern "C" void kernel_launch(void* const* d_in, const int* in_sizes, int n_in,
                              void* d_out, int out_size) {
    const float* fused_in = (const float*)d_in[0];
    const float* orig_x   = (const float*)d_in[1];
    const float* orig_y   = (const float*)d_in[2];
    const float* m_ln_g   = (const float*)d_in[3];
    const float* m_ln_b   = (const float*)d_in[4];
    const float* m_in_w   = (const float*)d_in[5];
    const float* m_conv_w = (const float*)d_in[6];
    const float* m_conv_b = (const float*)d_in[7];
    const float* m_xproj_w= (const float*)d_in[8];
    const float* m_dt_w   = (const float*)d_in[9];
    const float* m_dt_b   = (const float*)d_in[10];
    const float* m_Alog   = (const float*)d_in[11];
    const float* m_D      = (const float*)d_in[12];
    const float* m_out_w  = (const float*)d_in[13];
    const float* lnf_g    = (const float*)d_in[14];
    const float* lnf_b    = (const float*)d_in[15];
    const float* c1_w     = (const float*)d_in[16];
    const float* c1_b     = (const float*)d_in[17];
    const float* bn1_g    = (const float*)d_in[18];
    const float* bn1_b    = (const float*)d_in[19];
    const float* bn1_m    = (const float*)d_in[20];
    const float* bn1_v    = (const float*)d_in[21];
    const float* c2_w     = (const float*)d_in[22];
    const float* c2_b     = (const float*)d_in[23];
    const float* bn2_g    = (const float*)d_in[24];
    const float* bn2_b    = (const float*)d_in[25];
    const float* bn2_m    = (const float*)d_in[26];
    const float* bn2_v    = (const float*)d_in[27];
    const float* cce_w1   = (const float*)d_in[28];
    const float* cce_w2   = (const float*)d_in[29];
    const float* c3_w     = (const float*)d_in[30];
    const float* c3_b     = (const float*)d_in[31];
    float* out = (float*)d_out;

    float *p_fused, *p_h, *p_xz, *p_xm, *p_xdbl, *p_y, *p_img, *p_c1, *p_c2, *p_w1c, *p_w2c;
    cudaGetSymbolAddress((void**)&p_fused, g_fused);
    cudaGetSymbolAddress((void**)&p_h,     g_h);
    cudaGetSymbolAddress((void**)&p_xz,    g_xz);
    cudaGetSymbolAddress((void**)&p_xm,    g_xm);
    cudaGetSymbolAddress((void**)&p_xdbl,  g_xdbl);
    cudaGetSymbolAddress((void**)&p_y,     g_y);
    cudaGetSymbolAddress((void**)&p_img,   g_img);
    cudaGetSymbolAddress((void**)&p_c1,    g_c1);
    cudaGetSymbolAddress((void**)&p_c2,    g_c2);
    cudaGetSymbolAddress((void**)&p_w1c,   g_w1c);
    cudaGetSymbolAddress((void**)&p_w2c,   g_w2c);

    // launches 1-3: weight prep + first LN; #4 = cce_gate_part (profiled slot)
    make_wc_kernel<<<32, 256>>>(c1_w, p_w1c, 64*128);
    make_wc_kernel<<<8, 256>>>(c2_w, p_w2c, 32*64);
    ln_kernel<<<2048, 256>>>(fused_in, m_ln_g, m_ln_b, p_h);
    cce_gate_part<<<dim3(GSLAB, 16, 2), 256>>>(cce_w1, orig_x, orig_y);

    // ---- 3 Mamba blocks ----
    for (int i = 0; i < 3; i++) {
        const float* src = (i == 0) ? fused_in : p_fused;
        sgemm128<<<dim3(4, 128), 256>>>(p_h, m_in_w + (size_t)i*512*128, p_xz, 512, 128);
        dwconv_silu_kernel<<<16384, 256>>>(m_conv_w + i*DI*4, m_conv_b + i*DI);
        gemm_tn_kernel<<<dim3(1, 256), 256>>>(p_xm, m_xproj_w + (size_t)i*24*256, p_xdbl, 24, 256);
        scan_pass1<<<dim3(NSEG, 16), 256>>>(m_Alog + i*DI*8, m_dt_w + i*DI*8, m_dt_b + i*DI);
        scan_pass2<<<512, 256>>>();
        scan_pass3<<<dim3(NSEG, 16), 256>>>(m_Alog + i*DI*8, m_D + i*DI);
        int mode = (i < 2) ? 0 : 1;
        const float* gam = (i < 2) ? (m_ln_g + (i+1)*128) : m_ln_g;
        const float* bet = (i < 2) ? (m_ln_b + (i+1)*128) : m_ln_b;
        sgemm_out_ln<<<128, 256>>>(p_y, m_out_w + (size_t)i*128*256, src,
                                   gam, bet, p_fused, p_h, mode);
    }

    // ---- final LN -> NCHW image ----
    ln_final_kernel<<<2048, 256>>>(p_fused, lnf_g, lnf_b);

    // ---- conv1: up2 + 3x3 (128->64), bn, relu ----
    conv_up2_kernel<128, 64, 32, 64, 1><<<dim3(4, 8, 16), 256>>>(
        p_img, p_c1, p_w1c, c1_b, bn1_g, bn1_b, bn1_m, bn1_v);

    // ---- conv2: up2 + 3x3 (64->32), relu, bn ----
    conv_up2_kernel<64, 32, 64, 128, 2><<<dim3(16, 4, 16), 256>>>(
        p_c1, p_c2, p_w2c, c2_b, bn2_g, bn2_b, bn2_m, bn2_v);

    // ---- CCE apply (gates finalized in-kernel from partials) ----
    cce_apply_kernel<<<dim3(64, 16), 256>>>(cce_w2, orig_x, orig_y);

    // ---- conv3 + sigmoid -> output ----
    conv3_kernel<<<dim3(64, 16), 256>>>(c3_w, c3_b, out);
}

// round 15
// speedup vs baseline: 1.1100x; 1.0396x over previous
#include <cuda_runtime.h>
#include <math.h>

// ---------------- sizes ----------------
#define B_    16
#define L_    1024
#define DM    128
#define DI    256
#define MTOT  (B_*L_)      // 16384 rows
#define NSEG  64
#define LSEG  16
#define GSLAB 32

// ---------------- scratch (device globals; no allocation) ----------------
__device__ float g_fused[MTOT*DM];
__device__ float g_h    [MTOT*DM];
__device__ float g_xz   [MTOT*2*DI];      // [0,256)=xm_pre, [256,512)=z
__device__ float g_xm   [MTOT*DI];
__device__ float g_xdbl [MTOT*24];
__device__ float2 g_duw [MTOT*DI];        // per (m,d): {dt, w1=exp(-dt)} cached by pass1
__device__ float g_y    [MTOT*DI];
__device__ float g_agg  [B_*DI*NSEG*16];  // [b][d][seg][P8|H8]
__device__ float g_img  [B_*DM*1024];     // NCHW (16,128,32,32)
__device__ float g_c1   [B_*64*64*64];
__device__ float g_c2   [B_*32*128*128];
__device__ float g_w1c  [64*128*16];
__device__ float g_w2c  [32*64*16];
__device__ float g_gp   [2*16*GSLAB*64];

// ---------------- LayerNorm (warp per row of 128) ----------------
__global__ void ln_kernel(const float* __restrict__ x, const float* __restrict__ gam,
                          const float* __restrict__ bet, float* __restrict__ out) {
    int gw   = (blockIdx.x * blockDim.x + threadIdx.x) >> 5;
    int lane = threadIdx.x & 31;
    float4 v = *reinterpret_cast<const float4*>(x + (size_t)gw*128 + lane*4);
    float s  = v.x + v.y + v.z + v.w;
    float ss = v.x*v.x + v.y*v.y + v.z*v.z + v.w*v.w;
    #pragma unroll
    for (int o = 16; o; o >>= 1) {
        s  += __shfl_xor_sync(0xffffffffu, s,  o);
        ss += __shfl_xor_sync(0xffffffffu, ss, o);
    }
    float mean = s * (1.f/128.f);
    float var  = ss * (1.f/128.f) - mean*mean;
    float r    = rsqrtf(var + 1e-5f);
    float4 g4  = *reinterpret_cast<const float4*>(gam + lane*4);
    float4 b4  = *reinterpret_cast<const float4*>(bet + lane*4);
    float4 o4;
    o4.x = (v.x-mean)*r*g4.x + b4.x;
    o4.y = (v.y-mean)*r*g4.y + b4.y;
    o4.z = (v.z-mean)*r*g4.z + b4.z;
    o4.w = (v.w-mean)*r*g4.w + b4.w;
    *reinterpret_cast<float4*>(out + (size_t)gw*128 + lane*4) = o4;
}

__global__ void ln_final_kernel(const float* __restrict__ x, const float* __restrict__ gam,
                                const float* __restrict__ bet) {
    int gw   = (blockIdx.x * blockDim.x + threadIdx.x) >> 5;
    int lane = threadIdx.x & 31;
    float4 v = *reinterpret_cast<const float4*>(x + (size_t)gw*128 + lane*4);
    float s  = v.x + v.y + v.z + v.w;
    float ss = v.x*v.x + v.y*v.y + v.z*v.z + v.w*v.w;
    #pragma unroll
    for (int o = 16; o; o >>= 1) {
        s  += __shfl_xor_sync(0xffffffffu, s,  o);
        ss += __shfl_xor_sync(0xffffffffu, ss, o);
    }
    float mean = s * (1.f/128.f);
    float var  = ss * (1.f/128.f) - mean*mean;
    float r    = rsqrtf(var + 1e-5f);
    float4 g4  = *reinterpret_cast<const float4*>(gam + lane*4);
    float4 b4  = *reinterpret_cast<const float4*>(bet + lane*4);
    int b = gw >> 10, l = gw & 1023;
    size_t base = ((size_t)b*128 + lane*4)*1024 + l;
    g_img[base + 0*1024] = (v.x-mean)*r*g4.x + b4.x;
    g_img[base + 1*1024] = (v.y-mean)*r*g4.y + b4.y;
    g_img[base + 2*1024] = (v.z-mean)*r*g4.z + b4.z;
    g_img[base + 3*1024] = (v.w-mean)*r*g4.w + b4.w;
}

// ---------------- SGEMM 128x128x16: C[M,N] = A[M,K] @ W[N,K]^T (in_proj) ----------------
__global__ __launch_bounds__(256, 2) void sgemm128(const float* __restrict__ A,
        const float* __restrict__ W, float* __restrict__ C, int N, int K) {
    __shared__ float As[16][128];
    __shared__ float Bs[16][128];
    const int tid = threadIdx.x;
    const int m0 = blockIdx.y * 128, n0 = blockIdx.x * 128;
    const int tx = tid & 15, ty = tid >> 4;
    const int lr = tid >> 1, lc = (tid & 1) * 8;
    float acc[8][8];
    #pragma unroll
    for (int i = 0; i < 8; i++)
        #pragma unroll
        for (int j = 0; j < 8; j++) acc[i][j] = 0.f;

    const float* Ap = A + (size_t)(m0 + lr)*K + lc;
    const float* Wp = W + (size_t)(n0 + lr)*K + lc;

    for (int k0 = 0; k0 < K; k0 += 16) {
        float4 a0 = *reinterpret_cast<const float4*>(Ap + k0);
        float4 a1 = *reinterpret_cast<const float4*>(Ap + k0 + 4);
        float4 b0 = *reinterpret_cast<const float4*>(Wp + k0);
        float4 b1 = *reinterpret_cast<const float4*>(Wp + k0 + 4);
        __syncthreads();
        As[lc+0][lr]=a0.x; As[lc+1][lr]=a0.y; As[lc+2][lr]=a0.z; As[lc+3][lr]=a0.w;
        As[lc+4][lr]=a1.x; As[lc+5][lr]=a1.y; As[lc+6][lr]=a1.z; As[lc+7][lr]=a1.w;
        Bs[lc+0][lr]=b0.x; Bs[lc+1][lr]=b0.y; Bs[lc+2][lr]=b0.z; Bs[lc+3][lr]=b0.w;
        Bs[lc+4][lr]=b1.x; Bs[lc+5][lr]=b1.y; Bs[lc+6][lr]=b1.z; Bs[lc+7][lr]=b1.w;
        __syncthreads();
        #pragma unroll
        for (int k = 0; k < 16; k++) {
            float4 af0 = *reinterpret_cast<const float4*>(&As[k][ty*8]);
            float4 af1 = *reinterpret_cast<const float4*>(&As[k][ty*8+4]);
            float4 bf0 = *reinterpret_cast<const float4*>(&Bs[k][tx*8]);
            float4 bf1 = *reinterpret_cast<const float4*>(&Bs[k][tx*8+4]);
            float av[8] = {af0.x,af0.y,af0.z,af0.w,af1.x,af1.y,af1.z,af1.w};
            float bv[8] = {bf0.x,bf0.y,bf0.z,bf0.w,bf1.x,bf1.y,bf1.z,bf1.w};
            #pragma unroll
            for (int i = 0; i < 8; i++)
                #pragma unroll
                for (int j = 0; j < 8; j++)
                    acc[i][j] = fmaf(av[i], bv[j], acc[i][j]);
        }
    }
    #pragma unroll
    for (int i = 0; i < 8; i++) {
        size_t row = (size_t)(m0 + ty*8 + i)*N + n0 + tx*8;
        *reinterpret_cast<float4*>(C + row)     = make_float4(acc[i][0], acc[i][1], acc[i][2], acc[i][3]);
        *reinterpret_cast<float4*>(C + row + 4) = make_float4(acc[i][4], acc[i][5], acc[i][6], acc[i][7]);
    }
}

// ---------------- out_proj + residual + (next) LayerNorm fused ----------------
__global__ __launch_bounds__(256, 2) void sgemm_out_ln(const float* __restrict__ A,
        const float* __restrict__ W, const float* __restrict__ skip,
        const float* __restrict__ gam, const float* __restrict__ bet,
        float* __restrict__ fused_out, float* __restrict__ h_out, int mode) {
    const int K = 256, N = 128;
    __shared__ float As[16][128];
    __shared__ float Bs[16][128];
    const int tid = threadIdx.x;
    const int m0 = blockIdx.x * 128;
    const int tx = tid & 15, ty = tid >> 4;
    const int lr = tid >> 1, lc = (tid & 1) * 8;
    float acc[8][8];
    #pragma unroll
    for (int i = 0; i < 8; i++)
        #pragma unroll
        for (int j = 0; j < 8; j++) acc[i][j] = 0.f;

    const float* Ap = A + (size_t)(m0 + lr)*K + lc;
    const float* Wp = W + (size_t)lr*K + lc;

    for (int k0 = 0; k0 < K; k0 += 16) {
        float4 a0 = *reinterpret_cast<const float4*>(Ap + k0);
        float4 a1 = *reinterpret_cast<const float4*>(Ap + k0 + 4);
        float4 b0 = *reinterpret_cast<const float4*>(Wp + k0);
        float4 b1 = *reinterpret_cast<const float4*>(Wp + k0 + 4);
        __syncthreads();
        As[lc+0][lr]=a0.x; As[lc+1][lr]=a0.y; As[lc+2][lr]=a0.z; As[lc+3][lr]=a0.w;
        As[lc+4][lr]=a1.x; As[lc+5][lr]=a1.y; As[lc+6][lr]=a1.z; As[lc+7][lr]=a1.w;
        Bs[lc+0][lr]=b0.x; Bs[lc+1][lr]=b0.y; Bs[lc+2][lr]=b0.z; Bs[lc+3][lr]=b0.w;
        Bs[lc+4][lr]=b1.x; Bs[lc+5][lr]=b1.y; Bs[lc+6][lr]=b1.z; Bs[lc+7][lr]=b1.w;
        __syncthreads();
        #pragma unroll
        for (int k = 0; k < 16; k++) {
            float4 af0 = *reinterpret_cast<const float4*>(&As[k][ty*8]);
            float4 af1 = *reinterpret_cast<const float4*>(&As[k][ty*8+4]);
            float4 bf0 = *reinterpret_cast<const float4*>(&Bs[k][tx*8]);
            float4 bf1 = *reinterpret_cast<const float4*>(&Bs[k][tx*8+4]);
            float av[8] = {af0.x,af0.y,af0.z,af0.w,af1.x,af1.y,af1.z,af1.w};
            float bv[8] = {bf0.x,bf0.y,bf0.z,bf0.w,bf1.x,bf1.y,bf1.z,bf1.w};
            #pragma unroll
            for (int i = 0; i < 8; i++)
                #pragma unroll
                for (int j = 0; j < 8; j++)
                    acc[i][j] = fmaf(av[i], bv[j], acc[i][j]);
        }
    }
    float4 g0 = make_float4(0,0,0,0), g1 = g0, be0 = g0, be1 = g0;
    if (mode == 0) {
        g0  = *reinterpret_cast<const float4*>(gam + tx*8);
        g1  = *reinterpret_cast<const float4*>(gam + tx*8 + 4);
        be0 = *reinterpret_cast<const float4*>(bet + tx*8);
        be1 = *reinterpret_cast<const float4*>(bet + tx*8 + 4);
    }
    #pragma unroll
    for (int i = 0; i < 8; i++) {
        size_t row = (size_t)(m0 + ty*8 + i)*N + tx*8;
        float4 s0 = *reinterpret_cast<const float4*>(skip + row);
        float4 s1 = *reinterpret_cast<const float4*>(skip + row + 4);
        float v[8];
        v[0]=acc[i][0]+s0.x; v[1]=acc[i][1]+s0.y; v[2]=acc[i][2]+s0.z; v[3]=acc[i][3]+s0.w;
        v[4]=acc[i][4]+s1.x; v[5]=acc[i][5]+s1.y; v[6]=acc[i][6]+s1.z; v[7]=acc[i][7]+s1.w;
        *reinterpret_cast<float4*>(fused_out + row)     = make_float4(v[0],v[1],v[2],v[3]);
        *reinterpret_cast<float4*>(fused_out + row + 4) = make_float4(v[4],v[5],v[6],v[7]);
        if (mode == 0) {
            float s = 0.f, ss = 0.f;
            #pragma unroll
            for (int j = 0; j < 8; j++) { s += v[j]; ss += v[j]*v[j]; }
            #pragma unroll
            for (int o = 1; o < 16; o <<= 1) {
                s  += __shfl_xor_sync(0xffffffffu, s,  o);
                ss += __shfl_xor_sync(0xffffffffu, ss, o);
            }
            float mean = s * (1.f/128.f);
            float var  = ss * (1.f/128.f) - mean*mean;
            float r    = rsqrtf(var + 1e-5f);
            float h[8];
            h[0]=(v[0]-mean)*r*g0.x+be0.x; h[1]=(v[1]-mean)*r*g0.y+be0.y;
            h[2]=(v[2]-mean)*r*g0.z+be0.z; h[3]=(v[3]-mean)*r*g0.w+be0.w;
            h[4]=(v[4]-mean)*r*g1.x+be1.x; h[5]=(v[5]-mean)*r*g1.y+be1.y;
            h[6]=(v[6]-mean)*r*g1.z+be1.z; h[7]=(v[7]-mean)*r*g1.w+be1.w;
            *reinterpret_cast<float4*>(h_out + row)     = make_float4(h[0],h[1],h[2],h[3]);
            *reinterpret_cast<float4*>(h_out + row + 4) = make_float4(h[4],h[5],h[6],h[7]);
        }
    }
}

// ---------------- small-N GEMM (xproj, N=24, K=256) ----------------
__global__ void gemm_tn_kernel(const float* __restrict__ A, const float* __restrict__ W,
                               float* __restrict__ C, int N, int K) {
    __shared__ float As[16][68];
    __shared__ float Bs[16][68];
    int tid = threadIdx.x;
    int m0 = blockIdx.y * 64, n0 = blockIdx.x * 64;
    int tx = tid & 15, ty = tid >> 4;
    int lm = tid >> 2, lk = (tid & 3) * 4;
    float acc[4][4];
    #pragma unroll
    for (int i = 0; i < 4; i++)
        #pragma unroll
        for (int j = 0; j < 4; j++) acc[i][j] = 0.f;

    const float* Ap = A + (size_t)(m0 + lm)*K + lk;
    bool wok = (n0 + lm) < N;
    const float* Wp = W + (size_t)(n0 + lm)*K + lk;

    for (int k0 = 0; k0 < K; k0 += 16) {
        float4 a4 = *reinterpret_cast<const float4*>(Ap + k0);
        float4 w4 = wok ? *reinterpret_cast<const float4*>(Wp + k0)
                        : make_float4(0.f,0.f,0.f,0.f);
        As[lk+0][lm] = a4.x; As[lk+1][lm] = a4.y; As[lk+2][lm] = a4.z; As[lk+3][lm] = a4.w;
        Bs[lk+0][lm] = w4.x; Bs[lk+1][lm] = w4.y; Bs[lk+2][lm] = w4.z; Bs[lk+3][lm] = w4.w;
        __syncthreads();
        #pragma unroll
        for (int k = 0; k < 16; k++) {
            float4 av = *reinterpret_cast<const float4*>(&As[k][ty*4]);
            float4 bv = *reinterpret_cast<const float4*>(&Bs[k][tx*4]);
            float aa[4] = {av.x, av.y, av.z, av.w};
            float bb[4] = {bv.x, bv.y, bv.z, bv.w};
            #pragma unroll
            for (int i = 0; i < 4; i++)
                #pragma unroll
                for (int j = 0; j < 4; j++)
                    acc[i][j] = fmaf(aa[i], bb[j], acc[i][j]);
        }
        __syncthreads();
    }
    #pragma unroll
    for (int i = 0; i < 4; i++) {
        int m = m0 + ty*4 + i;
        #pragma unroll
        for (int j = 0; j < 4; j++) {
            int n = n0 + tx*4 + j;
            if (n < N) C[(size_t)m*N + n] = acc[i][j];
        }
    }
}

// ---------------- depthwise causal conv1d (k=4) + bias + SiLU ----------------
__global__ void dwconv_silu_kernel(const float* __restrict__ w, const float* __restrict__ bias) {
    int idx = blockIdx.x * blockDim.x + threadIdx.x;
    int d = idx & (DI-1);
    int m = idx >> 8;
    int l = m & 1023;
    float acc = bias[d];
    #pragma unroll
    for (int k = 0; k < 4; k++) {
        int ll = l + k - 3;
        if (ll >= 0) acc = fmaf(w[d*4 + k], g_xz[(size_t)(m + k - 3)*512 + d], acc);
    }
    g_xm[idx] = acc * __frcp_rn(1.f + __expf(-acc));
}

// ---------------- dt/w1 helper ----------------
__device__ __forceinline__ void dt_w1(float acc, float& dt, float& w1) {
    float e = __expf(acc);
    w1 = __frcp_rn(1.f + e);
    dt = (acc > 20.f) ? acc : __logf(1.f + e);
}

// ---------------- scan pass1: aggregates + (dt,w1) cache; xdbl staged in smem ----------------
__global__ __launch_bounds__(256) void scan_pass1(const float* __restrict__ Alog,
        const float* __restrict__ dtw, const float* __restrict__ dtb) {
    __shared__ float sA[2048], sW[2048], sB[256];
    __shared__ float sX[LSEG*24];          // 16 rows x 24 of g_xdbl
    int tid = threadIdx.x;
    int seg = blockIdx.x, b = blockIdx.y;
    int m0 = (b << 10) + (seg << 4);
    for (int i = tid; i < 2048; i += 256) { sA[i] = -expf(Alog[i]); sW[i] = dtw[i]; }
    sB[tid] = dtb[tid];
    for (int i = tid; i < LSEG*24; i += 256) sX[i] = g_xdbl[(size_t)m0*24 + i];
    __syncthreads();
    int d = tid;
    float A[8], wj[8];
    bool fast = true;
    #pragma unroll
    for (int n = 0; n < 8; n++) {
        A[n] = sA[d*8+n]; wj[n] = sW[d*8+n];
        fast = fast && (fabsf(A[n] + (float)(n+1)) < 1e-3f*(float)(n+1));
    }
    float bt = sB[d];
    float P[8], H[8];
    #pragma unroll
    for (int n = 0; n < 8; n++) { P[n] = 1.f; H[n] = 0.f; }
    #pragma unroll 2
    for (int l = 0; l < LSEG; l++) {
        int m = m0 + l;
        float u = g_xm[(size_t)m*256 + d];
        const float* r = sX + l*24;
        float acc = bt;
        #pragma unroll
        for (int j = 0; j < 8; j++) acc = fmaf(r[j], wj[j], acc);
        float dt, w1;
        dt_w1(acc, dt, w1);
        g_duw[(size_t)m*256 + d] = make_float2(dt, w1);
        float p[8];
        if (fast) {
            p[0] = w1;
            #pragma unroll
            for (int n = 1; n < 8; n++) p[n] = p[n-1]*w1;
        } else {
            #pragma unroll
            for (int n = 0; n < 8; n++) p[n] = __expf(dt*A[n]);
        }
        float du = dt * u;
        float4 B0 = *reinterpret_cast<const float4*>(r + 8);
        float4 B1 = *reinterpret_cast<const float4*>(r + 12);
        float Bv[8] = {B0.x,B0.y,B0.z,B0.w,B1.x,B1.y,B1.z,B1.w};
        #pragma unroll
        for (int n = 0; n < 8; n++) {
            P[n] *= p[n];
            H[n] = fmaf(p[n], H[n], du * Bv[n]);
        }
    }
    size_t base = ((size_t)((b*256 + d))*NSEG + seg) * 16;
    float4* o = reinterpret_cast<float4*>(g_agg + base);
    o[0] = make_float4(P[0],P[1],P[2],P[3]);
    o[1] = make_float4(P[4],P[5],P[6],P[7]);
    o[2] = make_float4(H[0],H[1],H[2],H[3]);
    o[3] = make_float4(H[4],H[5],H[6],H[7]);
}

// ---------------- scan pass2: PARALLEL warp-scan (R10 winner, NSEG=64) ----------------
__global__ __launch_bounds__(256) void scan_pass2() {
    int wid = threadIdx.x >> 5, lane = threadIdx.x & 31;
    size_t pair = (size_t)blockIdx.x * 8 + wid;
    float4* base = reinterpret_cast<float4*>(g_agg + pair * (NSEG*16));
    float4 a0 = base[lane*8 + 0], a1 = base[lane*8 + 1];
    float4 a2 = base[lane*8 + 2], a3 = base[lane*8 + 3];
    float4 b0 = base[lane*8 + 4], b1 = base[lane*8 + 5];
    float4 b2 = base[lane*8 + 6], b3 = base[lane*8 + 7];
    float Pa[8] = {a0.x,a0.y,a0.z,a0.w,a1.x,a1.y,a1.z,a1.w};
    float Ha[8] = {a2.x,a2.y,a2.z,a2.w,a3.x,a3.y,a3.z,a3.w};
    float P[8], H[8];
    P[0]=Pa[0]*b0.x; H[0]=fmaf(b0.x,Ha[0],b2.x);
    P[1]=Pa[1]*b0.y; H[1]=fmaf(b0.y,Ha[1],b2.y);
    P[2]=Pa[2]*b0.z; H[2]=fmaf(b0.z,Ha[2],b2.z);
    P[3]=Pa[3]*b0.w; H[3]=fmaf(b0.w,Ha[3],b2.w);
    P[4]=Pa[4]*b1.x; H[4]=fmaf(b1.x,Ha[4],b3.x);
    P[5]=Pa[5]*b1.y; H[5]=fmaf(b1.y,Ha[5],b3.y);
    P[6]=Pa[6]*b1.z; H[6]=fmaf(b1.z,Ha[6],b3.z);
    P[7]=Pa[7]*b1.w; H[7]=fmaf(b1.w,Ha[7],b3.w);
    #pragma unroll
    for (int dd = 1; dd < 32; dd <<= 1) {
        #pragma unroll
        for (int n = 0; n < 8; n++) {
            float po = __shfl_up_sync(0xffffffffu, P[n], dd);
            float ho = __shfl_up_sync(0xffffffffu, H[n], dd);
            if (lane >= dd) { H[n] = fmaf(P[n], ho, H[n]); P[n] *= po; }
        }
    }
    float hp[8];
    #pragma unroll
    for (int n = 0; n < 8; n++) {
        float h = __shfl_up_sync(0xffffffffu, H[n], 1);
        hp[n] = (lane == 0) ? 0.f : h;
    }
    base[lane*8 + 2] = make_float4(hp[0],hp[1],hp[2],hp[3]);
    base[lane*8 + 3] = make_float4(hp[4],hp[5],hp[6],hp[7]);
    float hq[8];
    #pragma unroll
    for (int n = 0; n < 8; n++) hq[n] = fmaf(Pa[n], hp[n], Ha[n]);
    base[lane*8 + 6] = make_float4(hq[0],hq[1],hq[2],hq[3]);
    base[lane*8 + 7] = make_float4(hq[4],hq[5],hq[6],hq[7]);
}

// ---------------- scan pass3: cached (dt,w1); xdbl staged in smem; emit y*silu(z) ----------------
__global__ __launch_bounds__(256) void scan_pass3(const float* __restrict__ Alog,
        const float* __restrict__ Dp) {
    __shared__ float sA[2048], sD[256];
    __shared__ float sX[LSEG*24];
    int tid = threadIdx.x;
    int seg = blockIdx.x, b = blockIdx.y;
    int m0 = (b << 10) + (seg << 4);
    for (int i = tid; i < 2048; i += 256) sA[i] = -expf(Alog[i]);
    sD[tid] = Dp[tid];
    for (int i = tid; i < LSEG*24; i += 256) sX[i] = g_xdbl[(size_t)m0*24 + i];
    __syncthreads();
    int d = tid;
    float A[8];
    bool fast = true;
    #pragma unroll
    for (int n = 0; n < 8; n++) {
        A[n] = sA[d*8+n];
        fast = fast && (fabsf(A[n] + (float)(n+1)) < 1e-3f*(float)(n+1));
    }
    float Dd = sD[d];
    size_t base = ((size_t)((b*256 + d))*NSEG + seg) * 16;
    float4 h0 = *reinterpret_cast<const float4*>(g_agg + base + 8);
    float4 h1 = *reinterpret_cast<const float4*>(g_agg + base + 12);
    float h[8] = {h0.x,h0.y,h0.z,h0.w,h1.x,h1.y,h1.z,h1.w};
    #pragma unroll 2
    for (int l = 0; l < LSEG; l++) {
        int m = m0 + l;
        float u = g_xm[(size_t)m*256 + d];
        float2 dw = g_duw[(size_t)m*256 + d];
        float dt = dw.x, w1 = dw.y;
        const float* r = sX + l*24;
        float p[8];
        if (fast) {
            p[0] = w1;
            #pragma unroll
            for (int n = 1; n < 8; n++) p[n] = p[n-1]*w1;
        } else {
            #pragma unroll
            for (int n = 0; n < 8; n++) p[n] = __expf(dt*A[n]);
        }
        float du = dt * u;
        float4 B0 = *reinterpret_cast<const float4*>(r + 8);
        float4 B1 = *reinterpret_cast<const float4*>(r + 12);
        float4 C0 = *reinterpret_cast<const float4*>(r + 16);
        float4 C1 = *reinterpret_cast<const float4*>(r + 20);
        float Bv[8] = {B0.x,B0.y,B0.z,B0.w,B1.x,B1.y,B1.z,B1.w};
        float Cv[8] = {C0.x,C0.y,C0.z,C0.w,C1.x,C1.y,C1.z,C1.w};
        float ys0 = 0.f, ys1 = 0.f;
        #pragma unroll
        for (int n = 0; n < 8; n++) {
            h[n] = fmaf(p[n], h[n], du * Bv[n]);
            if (n & 1) ys1 = fmaf(h[n], Cv[n], ys1);
            else       ys0 = fmaf(h[n], Cv[n], ys0);
        }
        float z  = g_xz[(size_t)m*512 + 256 + d];
        float sz = z * __frcp_rn(1.f + __expf(-z));
        g_y[(size_t)m*256 + d] = (ys0 + ys1 + u*Dd) * sz;
    }
}

// ---------------- combined 2x2 weights ----------------
__global__ void make_wc_kernel(const float* __restrict__ w, float* __restrict__ wc, int total) {
    int i = blockIdx.x * 256 + threadIdx.x;
    if (i >= total) return;
    const float* ws = w + (size_t)i*9;
    float t[3][4];
    #pragma unroll
    for (int ky = 0; ky < 3; ky++) {
        float w0 = ws[ky*3+0], w1 = ws[ky*3+1], w2 = ws[ky*3+2];
        t[ky][0] = w0;
        t[ky][1] = w1 + w2;
        t[ky][2] = w0 + w1;
        t[ky][3] = w2;
    }
    float* o = wc + (size_t)i*16;
    #pragma unroll
    for (int bk = 0; bk < 2; bk++) {
        o[(0*2+bk)*4 + 0*2 + 0] = t[0][bk*2+0];
        o[(0*2+bk)*4 + 0*2 + 1] = t[0][bk*2+1];
        o[(0*2+bk)*4 + 1*2 + 0] = t[1][bk*2+0] + t[2][bk*2+0];
        o[(0*2+bk)*4 + 1*2 + 1] = t[1][bk*2+1] + t[2][bk*2+1];
        o[(1*2+bk)*4 + 0*2 + 0] = t[0][bk*2+0] + t[1][bk*2+0];
        o[(1*2+bk)*4 + 0*2 + 1] = t[0][bk*2+1] + t[1][bk*2+1];
        o[(1*2+bk)*4 + 1*2 + 0] = t[2][bk*2+0];
        o[(1*2+bk)*4 + 1*2 + 1] = t[2][bk*2+1];
    }
}

// ---------------- up2+3x3 conv via 2x2 combined weights (R2 winner) ----------------
template<int CI, int CO, int SRCD, int OUTD, int MODE>
__global__ __launch_bounds__(256) void conv_up2_kernel(
        const float* __restrict__ in, float* __restrict__ out,
        const float* __restrict__ Wc, const float* __restrict__ bias,
        const float* __restrict__ bng, const float* __restrict__ bnb,
        const float* __restrict__ bnm, const float* __restrict__ bnv) {
    __shared__ float s_x[16][18][18];
    __shared__ float s_w[2048];
    const int tid = threadIdx.x;
    const int b   = blockIdx.z;
    const int cog = blockIdx.y;
    const int ntx = OUTD / 32;
    const int tyi = blockIdx.x / ntx, txi = blockIdx.x % ntx;
    const int oy0 = tyi*32, ox0 = txi*32;
    const int sy0 = oy0/2 - 1, sx0 = ox0/2 - 1;
    const int px = tid & 15, py = tid >> 4;
    const int pa = py & 1, pb = px & 1;
    const int p  = pa*2 + pb;

    int rbase[2], cbase[2];
    #pragma unroll
    for (int i = 0; i < 2; i++) {
        rbase[i] = ((py + 16*i) >> 1) + pa;
        cbase[i] = ((px + 16*i) >> 1) + pb;
    }

    float acc[8][4];
    #pragma unroll
    for (int c = 0; c < 8; c++)
        #pragma unroll
        for (int q = 0; q < 4; q++) acc[c][q] = 0.f;

    for (int cc = 0; cc < CI; cc += 16) {
        for (int idx = tid; idx < 16*324; idx += 256) {
            int ci = idx / 324; int rem = idx - ci*324;
            int r = rem / 18, c = rem - r*18;
            int sy = sy0 + r, sxp = sx0 + c;
            float v = 0.f;
            if (sy >= 0 && sy < SRCD && sxp >= 0 && sxp < SRCD)
                v = in[(((size_t)b*CI + cc + ci)*SRCD + sy)*SRCD + sxp];
            s_x[ci][r][c] = v;
        }
        for (int i = tid; i < 2048; i += 256) {
            int ci = i >> 7, rem = i & 127;
            int pp = rem >> 5, co = (rem >> 2) & 7, jk = i & 3;
            s_w[i] = Wc[((size_t)(cog*8 + co)*CI + cc + ci)*16 + pp*4 + jk];
        }
        __syncthreads();
        #pragma unroll 2
        for (int ci = 0; ci < 16; ci++) {
            float4 w4[8];
            #pragma unroll
            for (int co = 0; co < 8; co++)
                w4[co] = *reinterpret_cast<const float4*>(&s_w[((ci*4 + p)*8 + co)*4]);
            #pragma unroll
            for (int iq = 0; iq < 2; iq++)
                #pragma unroll
                for (int jq = 0; jq < 2; jq++) {
                    int q = iq*2 + jq;
                    float x00 = s_x[ci][rbase[iq]+0][cbase[jq]+0];
                    float x01 = s_x[ci][rbase[iq]+0][cbase[jq]+1];
                    float x10 = s_x[ci][rbase[iq]+1][cbase[jq]+0];
                    float x11 = s_x[ci][rbase[iq]+1][cbase[jq]+1];
                    #pragma unroll
                    for (int co = 0; co < 8; co++) {
                        float a = acc[co][q];
                        a = fmaf(w4[co].x, x00, a);
                        a = fmaf(w4[co].y, x01, a);
                        a = fmaf(w4[co].z, x10, a);
                        a = fmaf(w4[co].w, x11, a);
                        acc[co][q] = a;
                    }
                }
        }
        __syncthreads();
    }
    #pragma unroll
    for (int co = 0; co < 8; co++) {
        int c = cog*8 + co;
        float sc = bng[c] * rsqrtf(bnv[c] + 1e-5f);
        float sh2 = bnb[c] - bnm[c]*sc;
        float bsv = bias[c];
        #pragma unroll
        for (int q = 0; q < 4; q++) {
            int i = q >> 1, j = q & 1;
            int oy = oy0 + py + 16*i, ox = ox0 + px + 16*j;
            float v = acc[co][q] + bsv;
            v = (MODE == 1) ? fmaxf(v*sc + sh2, 0.f) : (fmaxf(v, 0.f)*sc + sh2);
            out[(((size_t)b*CO + c)*OUTD + oy)*OUTD + ox] = v;
        }
    }
}

// ---------------- CCE gate partials (R11/R12 winner) ----------------
__global__ __launch_bounds__(256) void cce_gate_part(const float* __restrict__ w1,
        const float* __restrict__ ox, const float* __restrict__ oy) {
    __shared__ float sw[1024];
    __shared__ float sx[64*36];
    __shared__ float red[2][8][32];
    int tid = threadIdx.x;
    for (int i = tid; i < 1024; i += 256) sw[i] = w1[i];
    __syncthreads();
    int which = blockIdx.z, b = blockIdx.y, slab = blockIdx.x;
    const float* base = (which ? oy : ox) + (size_t)b*32*16384;
    int c = tid & 31, g = tid >> 5;
    float4 w4[8];
    #pragma unroll
    for (int q = 0; q < 8; q++)
        w4[q] = *reinterpret_cast<const float4*>(&sw[c*32 + q*4]);
    float mx = -1e30f, sm = 0.f;
    int p0 = slab * (16384/GSLAB);
    #pragma unroll 1
    for (int it = 0; it < (16384/GSLAB)/64; it++) {
        int pt = p0 + it*64;
        __syncthreads();
        for (int i = tid; i < 512; i += 256) {
            int ci = i >> 4, p4 = (i & 15) * 4;
            float4 v = *reinterpret_cast<const float4*>(base + (size_t)ci*16384 + pt + p4);
            sx[(p4+0)*36 + ci] = v.x;
            sx[(p4+1)*36 + ci] = v.y;
            sx[(p4+2)*36 + ci] = v.z;
            sx[(p4+3)*36 + ci] = v.w;
        }
        __syncthreads();
        #pragma unroll
        for (int pp = 0; pp < 8; pp++) {
            const float* xr = &sx[(g*8 + pp)*36];
            float a = 0.f;
            #pragma unroll
            for (int q = 0; q < 8; q++) {
                float4 xv = *reinterpret_cast<const float4*>(xr + q*4);
                a = fmaf(w4[q].x, xv.x, a);
                a = fmaf(w4[q].y, xv.y, a);
                a = fmaf(w4[q].z, xv.z, a);
                a = fmaf(w4[q].w, xv.w, a);
            }
            mx = fmaxf(mx, a);
            sm += a;
        }
    }
    red[0][g][c] = mx;
    red[1][g][c] = sm;
    __syncthreads();
    if (tid < 32) {
        float m = red[0][0][tid], s = red[1][0][tid];
        #pragma unroll
        for (int w = 1; w < 8; w++) { m = fmaxf(m, red[0][w][tid]); s += red[1][w][tid]; }
        size_t o = ((size_t)(which*16 + b)*GSLAB + slab)*64 + tid*2;
        g_gp[o] = m; g_gp[o+1] = s;
    }
}

// ---------------- CCE apply (gate finalize folded in) ----------------
__global__ __launch_bounds__(256) void cce_apply_kernel(const float* __restrict__ w2,
                                 const float* __restrict__ ox, const float* __restrict__ oy) {
    __shared__ float sw[1024];
    __shared__ float sg[64];
    int tid = threadIdx.x;
    int b = blockIdx.y;
    for (int i = tid; i < 1024; i += 256) sw[i] = w2[i];
    if (tid < 64) {
        int which = tid >> 5, c = tid & 31;
        size_t base = ((size_t)(which*16 + b)*GSLAB)*64 + c*2;
        float m = -1e30f, s = 0.f;
        #pragma unroll
        for (int slab = 0; slab < GSLAB; slab++) {
            m = fmaxf(m, g_gp[base + slab*64]);
            s += g_gp[base + slab*64 + 1];
        }
        sg[tid] = __frcp_rn(1.f + __expf(-(m + s*(1.f/16384.f))));
    }
    __syncthreads();
    int pp = blockIdx.x * 256 + tid;
    float xv[32], yv[32];
    #pragma unroll
    for (int ci = 0; ci < 32; ci++) {
        xv[ci] = ox[((size_t)b*32 + ci)*16384 + pp];
        yv[ci] = oy[((size_t)b*32 + ci)*16384 + pp];
    }
    #pragma unroll 4
    for (int c = 0; c < 32; c++) {
        float r1 = 0.f, r2 = 0.f;
        #pragma unroll
        for (int q = 0; q < 8; q++) {
            float4 w4 = *reinterpret_cast<const float4*>(&sw[c*32 + q*4]);
            r1 = fmaf(w4.x, yv[q*4+0], r1); r2 = fmaf(w4.x, xv[q*4+0], r2);
            r1 = fmaf(w4.y, yv[q*4+1], r1); r2 = fmaf(w4.y, xv[q*4+1], r2);
            r1 = fmaf(w4.z, yv[q*4+2], r1); r2 = fmaf(w4.z, xv[q*4+2], r2);
            r1 = fmaf(w4.w, yv[q*4+3], r1); r2 = fmaf(w4.w, xv[q*4+3], r2);
        }
        size_t idx = ((size_t)b*32 + c)*16384 + pp;
        g_c2[idx] += sg[c]*r1 + sg[32+c]*r2;
    }
}

// ---------------- conv3 (32->1, 3x3) + sigmoid ----------------
__global__ void conv3_kernel(const float* __restrict__ w, const float* __restrict__ bias,
                             float* __restrict__ out) {
    __shared__ float sF[32][18][18];
    __shared__ float sw[288];
    int b = blockIdx.y;
    int tile = blockIdx.x;
    int ty0 = (tile >> 3) * 16, tx0 = (tile & 7) * 16;
    int tid = threadIdx.x;
    for (int idx = tid; idx < 32*324; idx += 256) {
        int ci = idx / 324; int rem = idx - ci*324;
        int r = rem / 18, c = rem - r*18;
        int gy = ty0 + r - 1, gx = tx0 + c - 1;
        float v = 0.f;
        if (gy >= 0 && gy < 128 && gx >= 0 && gx < 128)
            v = g_c2[(((size_t)b*32 + ci) << 14) + gy*128 + gx];
        sF[ci][r][c] = v;
    }
    for (int idx = tid; idx < 288; idx += 256) sw[idx] = w[idx];
    __syncthreads();
    int px = tid & 15, py = tid >> 4;
    float acc = bias[0];
    #pragma unroll 4
    for (int ci = 0; ci < 32; ci++)
        #pragma unroll
        for (int ky = 0; ky < 3; ky++)
            #pragma unroll
            for (int kx = 0; kx < 3; kx++)
                acc = fmaf(sw[ci*9 + ky*3 + kx], sF[ci][py + ky][px + kx], acc);
    out[((size_t)b << 14) + (ty0 + py)*128 + tx0 + px] = __frcp_rn(1.f + __expf(-acc));
}

// ---------------- launch ----------------
extern "C" void kernel_launch(void* const* d_in, const int* in_sizes, int n_in,
                              void* d_out, int out_size) {
    const float* fused_in = (const float*)d_in[0];
    const float* orig_x   = (const float*)d_in[1];
    const float* orig_y   = (const float*)d_in[2];
    const float* m_ln_g   = (const float*)d_in[3];
    const float* m_ln_b   = (const float*)d_in[4];
    const float* m_in_w   = (const float*)d_in[5];
    const float* m_conv_w = (const float*)d_in[6];
    const float* m_conv_b = (const float*)d_in[7];
    const float* m_xproj_w= (const float*)d_in[8];
    const float* m_dt_w   = (const float*)d_in[9];
    const float* m_dt_b   = (const float*)d_in[10];
    const float* m_Alog   = (const float*)d_in[11];
    const float* m_D      = (const float*)d_in[12];
    const float* m_out_w  = (const float*)d_in[13];
    const float* lnf_g    = (const float*)d_in[14];
    const float* lnf_b    = (const float*)d_in[15];
    const float* c1_w     = (const float*)d_in[16];
    const float* c1_b     = (const float*)d_in[17];
    const float* bn1_g    = (const float*)d_in[18];
    const float* bn1_b    = (const float*)d_in[19];
    const float* bn1_m    = (const float*)d_in[20];
    const float* bn1_v    = (const float*)d_in[21];
    const float* c2_w     = (const float*)d_in[22];
    const float* c2_b     = (const float*)d_in[23];
    const float* bn2_g    = (const float*)d_in[24];
    const float* bn2_b    = (const float*)d_in[25];
    const float* bn2_m    = (const float*)d_in[26];
    const float* bn2_v    = (const float*)d_in[27];
    const float* cce_w1   = (const float*)d_in[28];
    const float* cce_w2   = (const float*)d_in[29];
    const float* c3_w     = (const float*)d_in[30];
    const float* c3_b     = (const float*)d_in[31];
    float* out = (float*)d_out;

    float *p_fused, *p_h, *p_xz, *p_xm, *p_xdbl, *p_y, *p_img, *p_c1, *p_c2, *p_w1c, *p_w2c;
    cudaGetSymbolAddress((void**)&p_fused, g_fused);
    cudaGetSymbolAddress((void**)&p_h,     g_h);
    cudaGetSymbolAddress((void**)&p_xz,    g_xz);
    cudaGetSymbolAddress((void**)&p_xm,    g_xm);
    cudaGetSymbolAddress((void**)&p_xdbl,  g_xdbl);
    cudaGetSymbolAddress((void**)&p_y,     g_y);
    cudaGetSymbolAddress((void**)&p_img,   g_img);
    cudaGetSymbolAddress((void**)&p_c1,    g_c1);
    cudaGetSymbolAddress((void**)&p_c2,    g_c2);
    cudaGetSymbolAddress((void**)&p_w1c,   g_w1c);
    cudaGetSymbolAddress((void**)&p_w2c,   g_w2c);

    // launches 1-3: weight prep + first LN; #4 = cce_gate_part (profiled slot)
    make_wc_kernel<<<32, 256>>>(c1_w, p_w1c, 64*128);
    make_wc_kernel<<<8, 256>>>(c2_w, p_w2c, 32*64);
    ln_kernel<<<2048, 256>>>(fused_in, m_ln_g, m_ln_b, p_h);
    cce_gate_part<<<dim3(GSLAB, 16, 2), 256>>>(cce_w1, orig_x, orig_y);

    // ---- 3 Mamba blocks ----
    for (int i = 0; i < 3; i++) {
        const float* src = (i == 0) ? fused_in : p_fused;
        sgemm128<<<dim3(4, 128), 256>>>(p_h, m_in_w + (size_t)i*512*128, p_xz, 512, 128);
        dwconv_silu_kernel<<<16384, 256>>>(m_conv_w + i*DI*4, m_conv_b + i*DI);
        gemm_tn_kernel<<<dim3(1, 256), 256>>>(p_xm, m_xproj_w + (size_t)i*24*256, p_xdbl, 24, 256);
        scan_pass1<<<dim3(NSEG, 16), 256>>>(m_Alog + i*DI*8, m_dt_w + i*DI*8, m_dt_b + i*DI);
        scan_pass2<<<512, 256>>>();
        scan_pass3<<<dim3(NSEG, 16), 256>>>(m_Alog + i*DI*8, m_D + i*DI);
        int mode = (i < 2) ? 0 : 1;
        const float* gam = (i < 2) ? (m_ln_g + (i+1)*128) : m_ln_g;
        const float* bet = (i < 2) ? (m_ln_b + (i+1)*128) : m_ln_b;
        sgemm_out_ln<<<128, 256>>>(p_y, m_out_w + (size_t)i*128*256, src,
                                   gam, bet, p_fused, p_h, mode);
    }

    // ---- final LN -> NCHW image ----
    ln_final_kernel<<<2048, 256>>>(p_fused, lnf_g, lnf_b);

    // ---- conv1: up2 + 3x3 (128->64), bn, relu ----
    conv_up2_kernel<128, 64, 32, 64, 1><<<dim3(4, 8, 16), 256>>>(
        p_img, p_c1, p_w1c, c1_b, bn1_g, bn1_b, bn1_m, bn1_v);

    // ---- conv2: up2 + 3x3 (64->32), relu, bn ----
    conv_up2_kernel<64, 32, 64, 128, 2><<<dim3(16, 4, 16), 256>>>(
        p_c1, p_c2, p_w2c, c2_b, bn2_g, bn2_b, bn2_m, bn2_v);

    // ---- CCE apply (gates finalized in-kernel from partials) ----
    cce_apply_kernel<<<dim3(64, 16), 256>>>(cce_w2, orig_x, orig_y);

    // ---- conv3 + sigmoid -> output ----
    conv3_kernel<<<dim3(64, 16), 256>>>(c3_w, c3_b, out);
}

// round 16
// speedup vs baseline: 1.1317x; 1.0195x over previous
#include <cuda_runtime.h>
#include <math.h>

// ---------------- sizes ----------------
#define B_    16
#define L_    1024
#define DM    128
#define DI    256
#define MTOT  (B_*L_)      // 16384 rows
#define NSEG  64
#define LSEG  16
#define GSLAB 16

// ---------------- scratch (device globals; no allocation) ----------------
__device__ float g_fused[MTOT*DM];
__device__ float g_h    [MTOT*DM];
__device__ float g_xz   [MTOT*2*DI];      // [0,256)=xm_pre, [256,512)=z
__device__ float g_xm   [MTOT*DI];
__device__ float g_xdbl [MTOT*24];
__device__ float2 g_duw [MTOT*DI];        // per (m,d): {dt, w1=exp(-dt)} cached by pass1
__device__ float g_y    [MTOT*DI];
__device__ float g_agg  [B_*DI*NSEG*16];  // [b][d][seg][P8|H8]
__device__ float g_img  [B_*DM*1024];     // NCHW (16,128,32,32)
__device__ float g_c1   [B_*64*64*64];
__device__ float g_c2   [B_*32*128*128];
__device__ float g_w1c  [64*128*16];
__device__ float g_w2c  [32*64*16];
__device__ float g_gp   [2*16*GSLAB*64];

// ---------------- LayerNorm (warp per row of 128) ----------------
__global__ void ln_kernel(const float* __restrict__ x, const float* __restrict__ gam,
                          const float* __restrict__ bet, float* __restrict__ out) {
    int gw   = (blockIdx.x * blockDim.x + threadIdx.x) >> 5;
    int lane = threadIdx.x & 31;
    float4 v = *reinterpret_cast<const float4*>(x + (size_t)gw*128 + lane*4);
    float s  = v.x + v.y + v.z + v.w;
    float ss = v.x*v.x + v.y*v.y + v.z*v.z + v.w*v.w;
    #pragma unroll
    for (int o = 16; o; o >>= 1) {
        s  += __shfl_xor_sync(0xffffffffu, s,  o);
        ss += __shfl_xor_sync(0xffffffffu, ss, o);
    }
    float mean = s * (1.f/128.f);
    float var  = ss * (1.f/128.f) - mean*mean;
    float r    = rsqrtf(var + 1e-5f);
    float4 g4  = *reinterpret_cast<const float4*>(gam + lane*4);
    float4 b4  = *reinterpret_cast<const float4*>(bet + lane*4);
    float4 o4;
    o4.x = (v.x-mean)*r*g4.x + b4.x;
    o4.y = (v.y-mean)*r*g4.y + b4.y;
    o4.z = (v.z-mean)*r*g4.z + b4.z;
    o4.w = (v.w-mean)*r*g4.w + b4.w;
    *reinterpret_cast<float4*>(out + (size_t)gw*128 + lane*4) = o4;
}

__global__ void ln_final_kernel(const float* __restrict__ x, const float* __restrict__ gam,
                                const float* __restrict__ bet) {
    int gw   = (blockIdx.x * blockDim.x + threadIdx.x) >> 5;
    int lane = threadIdx.x & 31;
    float4 v = *reinterpret_cast<const float4*>(x + (size_t)gw*128 + lane*4);
    float s  = v.x + v.y + v.z + v.w;
    float ss = v.x*v.x + v.y*v.y + v.z*v.z + v.w*v.w;
    #pragma unroll
    for (int o = 16; o; o >>= 1) {
        s  += __shfl_xor_sync(0xffffffffu, s,  o);
        ss += __shfl_xor_sync(0xffffffffu, ss, o);
    }
    float mean = s * (1.f/128.f);
    float var  = ss * (1.f/128.f) - mean*mean;
    float r    = rsqrtf(var + 1e-5f);
    float4 g4  = *reinterpret_cast<const float4*>(gam + lane*4);
    float4 b4  = *reinterpret_cast<const float4*>(bet + lane*4);
    int b = gw >> 10, l = gw & 1023;
    size_t base = ((size_t)b*128 + lane*4)*1024 + l;
    g_img[base + 0*1024] = (v.x-mean)*r*g4.x + b4.x;
    g_img[base + 1*1024] = (v.y-mean)*r*g4.y + b4.y;
    g_img[base + 2*1024] = (v.z-mean)*r*g4.z + b4.z;
    g_img[base + 3*1024] = (v.w-mean)*r*g4.w + b4.w;
}

// ---------------- SGEMM 128x128x16: C[M,N] = A[M,K] @ W[N,K]^T (in_proj) ----------------
__global__ __launch_bounds__(256, 2) void sgemm128(const float* __restrict__ A,
        const float* __restrict__ W, float* __restrict__ C, int N, int K) {
    __shared__ float As[16][128];
    __shared__ float Bs[16][128];
    const int tid = threadIdx.x;
    const int m0 = blockIdx.y * 128, n0 = blockIdx.x * 128;
    const int tx = tid & 15, ty = tid >> 4;
    const int lr = tid >> 1, lc = (tid & 1) * 8;
    float acc[8][8];
    #pragma unroll
    for (int i = 0; i < 8; i++)
        #pragma unroll
        for (int j = 0; j < 8; j++) acc[i][j] = 0.f;

    const float* Ap = A + (size_t)(m0 + lr)*K + lc;
    const float* Wp = W + (size_t)(n0 + lr)*K + lc;

    for (int k0 = 0; k0 < K; k0 += 16) {
        float4 a0 = *reinterpret_cast<const float4*>(Ap + k0);
        float4 a1 = *reinterpret_cast<const float4*>(Ap + k0 + 4);
        float4 b0 = *reinterpret_cast<const float4*>(Wp + k0);
        float4 b1 = *reinterpret_cast<const float4*>(Wp + k0 + 4);
        __syncthreads();
        As[lc+0][lr]=a0.x; As[lc+1][lr]=a0.y; As[lc+2][lr]=a0.z; As[lc+3][lr]=a0.w;
        As[lc+4][lr]=a1.x; As[lc+5][lr]=a1.y; As[lc+6][lr]=a1.z; As[lc+7][lr]=a1.w;
        Bs[lc+0][lr]=b0.x; Bs[lc+1][lr]=b0.y; Bs[lc+2][lr]=b0.z; Bs[lc+3][lr]=b0.w;
        Bs[lc+4][lr]=b1.x; Bs[lc+5][lr]=b1.y; Bs[lc+6][lr]=b1.z; Bs[lc+7][lr]=b1.w;
        __syncthreads();
        #pragma unroll
        for (int k = 0; k < 16; k++) {
            float4 af0 = *reinterpret_cast<const float4*>(&As[k][ty*8]);
            float4 af1 = *reinterpret_cast<const float4*>(&As[k][ty*8+4]);
            float4 bf0 = *reinterpret_cast<const float4*>(&Bs[k][tx*8]);
            float4 bf1 = *reinterpret_cast<const float4*>(&Bs[k][tx*8+4]);
            float av[8] = {af0.x,af0.y,af0.z,af0.w,af1.x,af1.y,af1.z,af1.w};
            float bv[8] = {bf0.x,bf0.y,bf0.z,bf0.w,bf1.x,bf1.y,bf1.z,bf1.w};
            #pragma unroll
            for (int i = 0; i < 8; i++)
                #pragma unroll
                for (int j = 0; j < 8; j++)
                    acc[i][j] = fmaf(av[i], bv[j], acc[i][j]);
        }
    }
    #pragma unroll
    for (int i = 0; i < 8; i++) {
        size_t row = (size_t)(m0 + ty*8 + i)*N + n0 + tx*8;
        *reinterpret_cast<float4*>(C + row)     = make_float4(acc[i][0], acc[i][1], acc[i][2], acc[i][3]);
        *reinterpret_cast<float4*>(C + row + 4) = make_float4(acc[i][4], acc[i][5], acc[i][6], acc[i][7]);
    }
}

// ---------------- out_proj + residual + (next) LayerNorm fused ----------------
__global__ __launch_bounds__(256, 2) void sgemm_out_ln(const float* __restrict__ A,
        const float* __restrict__ W, const float* __restrict__ skip,
        const float* __restrict__ gam, const float* __restrict__ bet,
        float* __restrict__ fused_out, float* __restrict__ h_out, int mode) {
    const int K = 256, N = 128;
    __shared__ float As[16][128];
    __shared__ float Bs[16][128];
    const int tid = threadIdx.x;
    const int m0 = blockIdx.x * 128;
    const int tx = tid & 15, ty = tid >> 4;
    const int lr = tid >> 1, lc = (tid & 1) * 8;
    float acc[8][8];
    #pragma unroll
    for (int i = 0; i < 8; i++)
        #pragma unroll
        for (int j = 0; j < 8; j++) acc[i][j] = 0.f;

    const float* Ap = A + (size_t)(m0 + lr)*K + lc;
    const float* Wp = W + (size_t)lr*K + lc;

    for (int k0 = 0; k0 < K; k0 += 16) {
        float4 a0 = *reinterpret_cast<const float4*>(Ap + k0);
        float4 a1 = *reinterpret_cast<const float4*>(Ap + k0 + 4);
        float4 b0 = *reinterpret_cast<const float4*>(Wp + k0);
        float4 b1 = *reinterpret_cast<const float4*>(Wp + k0 + 4);
        __syncthreads();
        As[lc+0][lr]=a0.x; As[lc+1][lr]=a0.y; As[lc+2][lr]=a0.z; As[lc+3][lr]=a0.w;
        As[lc+4][lr]=a1.x; As[lc+5][lr]=a1.y; As[lc+6][lr]=a1.z; As[lc+7][lr]=a1.w;
        Bs[lc+0][lr]=b0.x; Bs[lc+1][lr]=b0.y; Bs[lc+2][lr]=b0.z; Bs[lc+3][lr]=b0.w;
        Bs[lc+4][lr]=b1.x; Bs[lc+5][lr]=b1.y; Bs[lc+6][lr]=b1.z; Bs[lc+7][lr]=b1.w;
        __syncthreads();
        #pragma unroll
        for (int k = 0; k < 16; k++) {
            float4 af0 = *reinterpret_cast<const float4*>(&As[k][ty*8]);
            float4 af1 = *reinterpret_cast<const float4*>(&As[k][ty*8+4]);
            float4 bf0 = *reinterpret_cast<const float4*>(&Bs[k][tx*8]);
            float4 bf1 = *reinterpret_cast<const float4*>(&Bs[k][tx*8+4]);
            float av[8] = {af0.x,af0.y,af0.z,af0.w,af1.x,af1.y,af1.z,af1.w};
            float bv[8] = {bf0.x,bf0.y,bf0.z,bf0.w,bf1.x,bf1.y,bf1.z,bf1.w};
            #pragma unroll
            for (int i = 0; i < 8; i++)
                #pragma unroll
                for (int j = 0; j < 8; j++)
                    acc[i][j] = fmaf(av[i], bv[j], acc[i][j]);
        }
    }
    float4 g0 = make_float4(0,0,0,0), g1 = g0, be0 = g0, be1 = g0;
    if (mode == 0) {
        g0  = *reinterpret_cast<const float4*>(gam + tx*8);
        g1  = *reinterpret_cast<const float4*>(gam + tx*8 + 4);
        be0 = *reinterpret_cast<const float4*>(bet + tx*8);
        be1 = *reinterpret_cast<const float4*>(bet + tx*8 + 4);
    }
    #pragma unroll
    for (int i = 0; i < 8; i++) {
        size_t row = (size_t)(m0 + ty*8 + i)*N + tx*8;
        float4 s0 = *reinterpret_cast<const float4*>(skip + row);
        float4 s1 = *reinterpret_cast<const float4*>(skip + row + 4);
        float v[8];
        v[0]=acc[i][0]+s0.x; v[1]=acc[i][1]+s0.y; v[2]=acc[i][2]+s0.z; v[3]=acc[i][3]+s0.w;
        v[4]=acc[i][4]+s1.x; v[5]=acc[i][5]+s1.y; v[6]=acc[i][6]+s1.z; v[7]=acc[i][7]+s1.w;
        *reinterpret_cast<float4*>(fused_out + row)     = make_float4(v[0],v[1],v[2],v[3]);
        *reinterpret_cast<float4*>(fused_out + row + 4) = make_float4(v[4],v[5],v[6],v[7]);
        if (mode == 0) {
            float s = 0.f, ss = 0.f;
            #pragma unroll
            for (int j = 0; j < 8; j++) { s += v[j]; ss += v[j]*v[j]; }
            #pragma unroll
            for (int o = 1; o < 16; o <<= 1) {
                s  += __shfl_xor_sync(0xffffffffu, s,  o);
                ss += __shfl_xor_sync(0xffffffffu, ss, o);
            }
            float mean = s * (1.f/128.f);
            float var  = ss * (1.f/128.f) - mean*mean;
            float r    = rsqrtf(var + 1e-5f);
            float h[8];
            h[0]=(v[0]-mean)*r*g0.x+be0.x; h[1]=(v[1]-mean)*r*g0.y+be0.y;
            h[2]=(v[2]-mean)*r*g0.z+be0.z; h[3]=(v[3]-mean)*r*g0.w+be0.w;
            h[4]=(v[4]-mean)*r*g1.x+be1.x; h[5]=(v[5]-mean)*r*g1.y+be1.y;
            h[6]=(v[6]-mean)*r*g1.z+be1.z; h[7]=(v[7]-mean)*r*g1.w+be1.w;
            *reinterpret_cast<float4*>(h_out + row)     = make_float4(h[0],h[1],h[2],h[3]);
            *reinterpret_cast<float4*>(h_out + row + 4) = make_float4(h[4],h[5],h[6],h[7]);
        }
    }
}

// ---------------- small-N GEMM (xproj, N=24, K=256) ----------------
__global__ void gemm_tn_kernel(const float* __restrict__ A, const float* __restrict__ W,
                               float* __restrict__ C, int N, int K) {
    __shared__ float As[16][68];
    __shared__ float Bs[16][68];
    int tid = threadIdx.x;
    int m0 = blockIdx.y * 64, n0 = blockIdx.x * 64;
    int tx = tid & 15, ty = tid >> 4;
    int lm = tid >> 2, lk = (tid & 3) * 4;
    float acc[4][4];
    #pragma unroll
    for (int i = 0; i < 4; i++)
        #pragma unroll
        for (int j = 0; j < 4; j++) acc[i][j] = 0.f;

    const float* Ap = A + (size_t)(m0 + lm)*K + lk;
    bool wok = (n0 + lm) < N;
    const float* Wp = W + (size_t)(n0 + lm)*K + lk;

    for (int k0 = 0; k0 < K; k0 += 16) {
        float4 a4 = *reinterpret_cast<const float4*>(Ap + k0);
        float4 w4 = wok ? *reinterpret_cast<const float4*>(Wp + k0)
                        : make_float4(0.f,0.f,0.f,0.f);
        As[lk+0][lm] = a4.x; As[lk+1][lm] = a4.y; As[lk+2][lm] = a4.z; As[lk+3][lm] = a4.w;
        Bs[lk+0][lm] = w4.x; Bs[lk+1][lm] = w4.y; Bs[lk+2][lm] = w4.z; Bs[lk+3][lm] = w4.w;
        __syncthreads();
        #pragma unroll
        for (int k = 0; k < 16; k++) {
            float4 av = *reinterpret_cast<const float4*>(&As[k][ty*4]);
            float4 bv = *reinterpret_cast<const float4*>(&Bs[k][tx*4]);
            float aa[4] = {av.x, av.y, av.z, av.w};
            float bb[4] = {bv.x, bv.y, bv.z, bv.w};
            #pragma unroll
            for (int i = 0; i < 4; i++)
                #pragma unroll
                for (int j = 0; j < 4; j++)
                    acc[i][j] = fmaf(aa[i], bb[j], acc[i][j]);
        }
        __syncthreads();
    }
    #pragma unroll
    for (int i = 0; i < 4; i++) {
        int m = m0 + ty*4 + i;
        #pragma unroll
        for (int j = 0; j < 4; j++) {
            int n = n0 + tx*4 + j;
            if (n < N) C[(size_t)m*N + n] = acc[i][j];
        }
    }
}

// ---------------- depthwise causal conv1d (k=4) + bias + SiLU ----------------
__global__ void dwconv_silu_kernel(const float* __restrict__ w, const float* __restrict__ bias) {
    int idx = blockIdx.x * blockDim.x + threadIdx.x;
    int d = idx & (DI-1);
    int m = idx >> 8;
    int l = m & 1023;
    float acc = bias[d];
    #pragma unroll
    for (int k = 0; k < 4; k++) {
        int ll = l + k - 3;
        if (ll >= 0) acc = fmaf(w[d*4 + k], g_xz[(size_t)(m + k - 3)*512 + d], acc);
    }
    g_xm[idx] = acc * __frcp_rn(1.f + __expf(-acc));
}

// ---------------- dt/w1 helper ----------------
__device__ __forceinline__ void dt_w1(float acc, float& dt, float& w1) {
    float e = __expf(acc);
    w1 = __frcp_rn(1.f + e);
    dt = (acc > 20.f) ? acc : __logf(1.f + e);
}

// ---------------- scan pass1: aggregates + (dt,w1) cache; xdbl staged in smem ----------------
__global__ __launch_bounds__(256) void scan_pass1(const float* __restrict__ Alog,
        const float* __restrict__ dtw, const float* __restrict__ dtb) {
    __shared__ float sA[2048], sW[2048], sB[256];
    __shared__ float sX[LSEG*24];
    int tid = threadIdx.x;
    int seg = blockIdx.x, b = blockIdx.y;
    int m0 = (b << 10) + (seg << 4);
    for (int i = tid; i < 2048; i += 256) { sA[i] = -expf(Alog[i]); sW[i] = dtw[i]; }
    sB[tid] = dtb[tid];
    for (int i = tid; i < LSEG*24; i += 256) sX[i] = g_xdbl[(size_t)m0*24 + i];
    __syncthreads();
    int d = tid;
    float A[8], wj[8];
    bool fast = true;
    #pragma unroll
    for (int n = 0; n < 8; n++) {
        A[n] = sA[d*8+n]; wj[n] = sW[d*8+n];
        fast = fast && (fabsf(A[n] + (float)(n+1)) < 1e-3f*(float)(n+1));
    }
    float bt = sB[d];
    float P[8], H[8];
    #pragma unroll
    for (int n = 0; n < 8; n++) { P[n] = 1.f; H[n] = 0.f; }
    #pragma unroll 2
    for (int l = 0; l < LSEG; l++) {
        int m = m0 + l;
        float u = g_xm[(size_t)m*256 + d];
        const float* r = sX + l*24;
        float acc = bt;
        #pragma unroll
        for (int j = 0; j < 8; j++) acc = fmaf(r[j], wj[j], acc);
        float dt, w1;
        dt_w1(acc, dt, w1);
        g_duw[(size_t)m*256 + d] = make_float2(dt, w1);
        float p[8];
        if (fast) {
            p[0] = w1;
            #pragma unroll
            for (int n = 1; n < 8; n++) p[n] = p[n-1]*w1;
        } else {
            #pragma unroll
            for (int n = 0; n < 8; n++) p[n] = __expf(dt*A[n]);
        }
        float du = dt * u;
        float4 B0 = *reinterpret_cast<const float4*>(r + 8);
        float4 B1 = *reinterpret_cast<const float4*>(r + 12);
        float Bv[8] = {B0.x,B0.y,B0.z,B0.w,B1.x,B1.y,B1.z,B1.w};
        #pragma unroll
        for (int n = 0; n < 8; n++) {
            P[n] *= p[n];
            H[n] = fmaf(p[n], H[n], du * Bv[n]);
        }
    }
    size_t base = ((size_t)((b*256 + d))*NSEG + seg) * 16;
    float4* o = reinterpret_cast<float4*>(g_agg + base);
    o[0] = make_float4(P[0],P[1],P[2],P[3]);
    o[1] = make_float4(P[4],P[5],P[6],P[7]);
    o[2] = make_float4(H[0],H[1],H[2],H[3]);
    o[3] = make_float4(H[4],H[5],H[6],H[7]);
}

// ---------------- scan pass2: PARALLEL warp-scan (R10 winner, NSEG=64) ----------------
__global__ __launch_bounds__(256) void scan_pass2() {
    int wid = threadIdx.x >> 5, lane = threadIdx.x & 31;
    size_t pair = (size_t)blockIdx.x * 8 + wid;
    float4* base = reinterpret_cast<float4*>(g_agg + pair * (NSEG*16));
    float4 a0 = base[lane*8 + 0], a1 = base[lane*8 + 1];
    float4 a2 = base[lane*8 + 2], a3 = base[lane*8 + 3];
    float4 b0 = base[lane*8 + 4], b1 = base[lane*8 + 5];
    float4 b2 = base[lane*8 + 6], b3 = base[lane*8 + 7];
    float Pa[8] = {a0.x,a0.y,a0.z,a0.w,a1.x,a1.y,a1.z,a1.w};
    float Ha[8] = {a2.x,a2.y,a2.z,a2.w,a3.x,a3.y,a3.z,a3.w};
    float P[8], H[8];
    P[0]=Pa[0]*b0.x; H[0]=fmaf(b0.x,Ha[0],b2.x);
    P[1]=Pa[1]*b0.y; H[1]=fmaf(b0.y,Ha[1],b2.y);
    P[2]=Pa[2]*b0.z; H[2]=fmaf(b0.z,Ha[2],b2.z);
    P[3]=Pa[3]*b0.w; H[3]=fmaf(b0.w,Ha[3],b2.w);
    P[4]=Pa[4]*b1.x; H[4]=fmaf(b1.x,Ha[4],b3.x);
    P[5]=Pa[5]*b1.y; H[5]=fmaf(b1.y,Ha[5],b3.y);
    P[6]=Pa[6]*b1.z; H[6]=fmaf(b1.z,Ha[6],b3.z);
    P[7]=Pa[7]*b1.w; H[7]=fmaf(b1.w,Ha[7],b3.w);
    #pragma unroll
    for (int dd = 1; dd < 32; dd <<= 1) {
        #pragma unroll
        for (int n = 0; n < 8; n++) {
            float po = __shfl_up_sync(0xffffffffu, P[n], dd);
            float ho = __shfl_up_sync(0xffffffffu, H[n], dd);
            if (lane >= dd) { H[n] = fmaf(P[n], ho, H[n]); P[n] *= po; }
        }
    }
    float hp[8];
    #pragma unroll
    for (int n = 0; n < 8; n++) {
        float h = __shfl_up_sync(0xffffffffu, H[n], 1);
        hp[n] = (lane == 0) ? 0.f : h;
    }
    base[lane*8 + 2] = make_float4(hp[0],hp[1],hp[2],hp[3]);
    base[lane*8 + 3] = make_float4(hp[4],hp[5],hp[6],hp[7]);
    float hq[8];
    #pragma unroll
    for (int n = 0; n < 8; n++) hq[n] = fmaf(Pa[n], hp[n], Ha[n]);
    base[lane*8 + 6] = make_float4(hq[0],hq[1],hq[2],hq[3]);
    base[lane*8 + 7] = make_float4(hq[4],hq[5],hq[6],hq[7]);
}

// ---------------- scan pass3: cached (dt,w1); xdbl staged in smem; emit y*silu(z) ----------------
__global__ __launch_bounds__(256) void scan_pass3(const float* __restrict__ Alog,
        const float* __restrict__ Dp) {
    __shared__ float sA[2048], sD[256];
    __shared__ float sX[LSEG*24];
    int tid = threadIdx.x;
    int seg = blockIdx.x, b = blockIdx.y;
    int m0 = (b << 10) + (seg << 4);
    for (int i = tid; i < 2048; i += 256) sA[i] = -expf(Alog[i]);
    sD[tid] = Dp[tid];
    for (int i = tid; i < LSEG*24; i += 256) sX[i] = g_xdbl[(size_t)m0*24 + i];
    __syncthreads();
    int d = tid;
    float A[8];
    bool fast = true;
    #pragma unroll
    for (int n = 0; n < 8; n++) {
        A[n] = sA[d*8+n];
        fast = fast && (fabsf(A[n] + (float)(n+1)) < 1e-3f*(float)(n+1));
    }
    float Dd = sD[d];
    size_t base = ((size_t)((b*256 + d))*NSEG + seg) * 16;
    float4 h0 = *reinterpret_cast<const float4*>(g_agg + base + 8);
    float4 h1 = *reinterpret_cast<const float4*>(g_agg + base + 12);
    float h[8] = {h0.x,h0.y,h0.z,h0.w,h1.x,h1.y,h1.z,h1.w};
    #pragma unroll 2
    for (int l = 0; l < LSEG; l++) {
        int m = m0 + l;
        float u = g_xm[(size_t)m*256 + d];
        float2 dw = g_duw[(size_t)m*256 + d];
        float dt = dw.x, w1 = dw.y;
        const float* r = sX + l*24;
        float p[8];
        if (fast) {
            p[0] = w1;
            #pragma unroll
            for (int n = 1; n < 8; n++) p[n] = p[n-1]*w1;
        } else {
            #pragma unroll
            for (int n = 0; n < 8; n++) p[n] = __expf(dt*A[n]);
        }
        float du = dt * u;
        float4 B0 = *reinterpret_cast<const float4*>(r + 8);
        float4 B1 = *reinterpret_cast<const float4*>(r + 12);
        float4 C0 = *reinterpret_cast<const float4*>(r + 16);
        float4 C1 = *reinterpret_cast<const float4*>(r + 20);
        float Bv[8] = {B0.x,B0.y,B0.z,B0.w,B1.x,B1.y,B1.z,B1.w};
        float Cv[8] = {C0.x,C0.y,C0.z,C0.w,C1.x,C1.y,C1.z,C1.w};
        float ys0 = 0.f, ys1 = 0.f;
        #pragma unroll
        for (int n = 0; n < 8; n++) {
            h[n] = fmaf(p[n], h[n], du * Bv[n]);
            if (n & 1) ys1 = fmaf(h[n], Cv[n], ys1);
            else       ys0 = fmaf(h[n], Cv[n], ys0);
        }
        float z  = g_xz[(size_t)m*512 + 256 + d];
        float sz = z * __frcp_rn(1.f + __expf(-z));
        g_y[(size_t)m*256 + d] = (ys0 + ys1 + u*Dd) * sz;
    }
}

// ---------------- combined 2x2 weights ----------------
__global__ void make_wc_kernel(const float* __restrict__ w, float* __restrict__ wc, int total) {
    int i = blockIdx.x * 256 + threadIdx.x;
    if (i >= total) return;
    const float* ws = w + (size_t)i*9;
    float t[3][4];
    #pragma unroll
    for (int ky = 0; ky < 3; ky++) {
        float w0 = ws[ky*3+0], w1 = ws[ky*3+1], w2 = ws[ky*3+2];
        t[ky][0] = w0;
        t[ky][1] = w1 + w2;
        t[ky][2] = w0 + w1;
        t[ky][3] = w2;
    }
    float* o = wc + (size_t)i*16;
    #pragma unroll
    for (int bk = 0; bk < 2; bk++) {
        o[(0*2+bk)*4 + 0*2 + 0] = t[0][bk*2+0];
        o[(0*2+bk)*4 + 0*2 + 1] = t[0][bk*2+1];
        o[(0*2+bk)*4 + 1*2 + 0] = t[1][bk*2+0] + t[2][bk*2+0];
        o[(0*2+bk)*4 + 1*2 + 1] = t[1][bk*2+1] + t[2][bk*2+1];
        o[(1*2+bk)*4 + 0*2 + 0] = t[0][bk*2+0] + t[1][bk*2+0];
        o[(1*2+bk)*4 + 0*2 + 1] = t[0][bk*2+1] + t[1][bk*2+1];
        o[(1*2+bk)*4 + 1*2 + 0] = t[2][bk*2+0];
        o[(1*2+bk)*4 + 1*2 + 1] = t[2][bk*2+1];
    }
}

// ---------------- up2+3x3 conv via 2x2 combined weights (R2 winner) ----------------
template<int CI, int CO, int SRCD, int OUTD, int MODE>
__global__ __launch_bounds__(256) void conv_up2_kernel(
        const float* __restrict__ in, float* __restrict__ out,
        const float* __restrict__ Wc, const float* __restrict__ bias,
        const float* __restrict__ bng, const float* __restrict__ bnb,
        const float* __restrict__ bnm, const float* __restrict__ bnv) {
    __shared__ float s_x[16][18][18];
    __shared__ float s_w[2048];
    const int tid = threadIdx.x;
    const int b   = blockIdx.z;
    const int cog = blockIdx.y;
    const int ntx = OUTD / 32;
    const int tyi = blockIdx.x / ntx, txi = blockIdx.x % ntx;
    const int oy0 = tyi*32, ox0 = txi*32;
    const int sy0 = oy0/2 - 1, sx0 = ox0/2 - 1;
    const int px = tid & 15, py = tid >> 4;
    const int pa = py & 1, pb = px & 1;
    const int p  = pa*2 + pb;

    int rbase[2], cbase[2];
    #pragma unroll
    for (int i = 0; i < 2; i++) {
        rbase[i] = ((py + 16*i) >> 1) + pa;
        cbase[i] = ((px + 16*i) >> 1) + pb;
    }

    float acc[8][4];
    #pragma unroll
    for (int c = 0; c < 8; c++)
        #pragma unroll
        for (int q = 0; q < 4; q++) acc[c][q] = 0.f;

    for (int cc = 0; cc < CI; cc += 16) {
        for (int idx = tid; idx < 16*324; idx += 256) {
            int ci = idx / 324; int rem = idx - ci*324;
            int r = rem / 18, c = rem - r*18;
            int sy = sy0 + r, sxp = sx0 + c;
            float v = 0.f;
            if (sy >= 0 && sy < SRCD && sxp >= 0 && sxp < SRCD)
                v = in[(((size_t)b*CI + cc + ci)*SRCD + sy)*SRCD + sxp];
            s_x[ci][r][c] = v;
        }
        for (int i = tid; i < 2048; i += 256) {
            int ci = i >> 7, rem = i & 127;
            int pp = rem >> 5, co = (rem >> 2) & 7, jk = i & 3;
            s_w[i] = Wc[((size_t)(cog*8 + co)*CI + cc + ci)*16 + pp*4 + jk];
        }
        __syncthreads();
        #pragma unroll 2
        for (int ci = 0; ci < 16; ci++) {
            float4 w4[8];
            #pragma unroll
            for (int co = 0; co < 8; co++)
                w4[co] = *reinterpret_cast<const float4*>(&s_w[((ci*4 + p)*8 + co)*4]);
            #pragma unroll
            for (int iq = 0; iq < 2; iq++)
                #pragma unroll
                for (int jq = 0; jq < 2; jq++) {
                    int q = iq*2 + jq;
                    float x00 = s_x[ci][rbase[iq]+0][cbase[jq]+0];
                    float x01 = s_x[ci][rbase[iq]+0][cbase[jq]+1];
                    float x10 = s_x[ci][rbase[iq]+1][cbase[jq]+0];
                    float x11 = s_x[ci][rbase[iq]+1][cbase[jq]+1];
                    #pragma unroll
                    for (int co = 0; co < 8; co++) {
                        float a = acc[co][q];
                        a = fmaf(w4[co].x, x00, a);
                        a = fmaf(w4[co].y, x01, a);
                        a = fmaf(w4[co].z, x10, a);
                        a = fmaf(w4[co].w, x11, a);
                        acc[co][q] = a;
                    }
                }
        }
        __syncthreads();
    }
    #pragma unroll
    for (int co = 0; co < 8; co++) {
        int c = cog*8 + co;
        float sc = bng[c] * rsqrtf(bnv[c] + 1e-5f);
        float sh2 = bnb[c] - bnm[c]*sc;
        float bsv = bias[c];
        #pragma unroll
        for (int q = 0; q < 4; q++) {
            int i = q >> 1, j = q & 1;
            int oy = oy0 + py + 16*i, ox = ox0 + px + 16*j;
            float v = acc[co][q] + bsv;
            v = (MODE == 1) ? fmaxf(v*sc + sh2, 0.f) : (fmaxf(v, 0.f)*sc + sh2);
            out[(((size_t)b*CO + c)*OUTD + oy)*OUTD + ox] = v;
        }
    }
}

// ---------------- CCE gate partials: thread-per-pixel, warp-butterfly reduction ----------------
// block = (slab16, b, which); thread owns pixel; lane c keeps channel c's (mx,sm)
__global__ __launch_bounds__(256) void cce_gate_part(const float* __restrict__ w1,
        const float* __restrict__ ox, const float* __restrict__ oy) {
    __shared__ float sw[1024];
    __shared__ float red[2][8][32];
    int tid = threadIdx.x;
    int lane = tid & 31, wid = tid >> 5;
    for (int i = tid; i < 1024; i += 256) sw[i] = w1[i];
    __syncthreads();
    int which = blockIdx.z, b = blockIdx.y, slab = blockIdx.x;
    const float* base = (which ? oy : ox) + (size_t)b*32*16384;
    float mx = -1e30f, sm = 0.f;      // state for channel = lane
    int p0 = slab * (16384/GSLAB);    // 1024 px per block
    #pragma unroll 1
    for (int it = 0; it < (16384/GSLAB)/256; it++) {   // 4 iters of 256 px
        int pp = p0 + it*256 + tid;
        float xv[32];
        #pragma unroll
        for (int ci = 0; ci < 32; ci++) xv[ci] = base[(size_t)ci*16384 + pp];
        #pragma unroll 4
        for (int c = 0; c < 32; c++) {
            float a = 0.f;
            #pragma unroll
            for (int q = 0; q < 8; q++) {
                float4 w4 = *reinterpret_cast<const float4*>(&sw[c*32 + q*4]);
                a = fmaf(w4.x, xv[q*4+0], a);
                a = fmaf(w4.y, xv[q*4+1], a);
                a = fmaf(w4.z, xv[q*4+2], a);
                a = fmaf(w4.w, xv[q*4+3], a);
            }
            float m = a, s = a;
            #pragma unroll
            for (int o = 16; o; o >>= 1) {
                m = fmaxf(m, __shfl_xor_sync(0xffffffffu, m, o));
                s += __shfl_xor_sync(0xffffffffu, s, o);
            }
            if (lane == c) { mx = fmaxf(mx, m); sm += s; }
        }
    }
    red[0][wid][lane] = mx;
    red[1][wid][lane] = sm;
    __syncthreads();
    if (tid < 32) {
        float m = red[0][0][tid], s = red[1][0][tid];
        #pragma unroll
        for (int w = 1; w < 8; w++) { m = fmaxf(m, red[0][w][tid]); s += red[1][w][tid]; }
        size_t o = ((size_t)(which*16 + b)*GSLAB + slab)*64 + tid*2;
        g_gp[o] = m; g_gp[o+1] = s;
    }
}

// ---------------- CCE apply (gate finalize folded in) ----------------
__global__ __launch_bounds__(256) void cce_apply_kernel(const float* __restrict__ w2,
                                 const float* __restrict__ ox, const float* __restrict__ oy) {
    __shared__ float sw[1024];
    __shared__ float sg[64];
    int tid = threadIdx.x;
    int b = blockIdx.y;
    for (int i = tid; i < 1024; i += 256) sw[i] = w2[i];
    if (tid < 64) {
        int which = tid >> 5, c = tid & 31;
        size_t base = ((size_t)(which*16 + b)*GSLAB)*64 + c*2;
        float m = -1e30f, s = 0.f;
        #pragma unroll
        for (int slab = 0; slab < GSLAB; slab++) {
            m = fmaxf(m, g_gp[base + slab*64]);
            s += g_gp[base + slab*64 + 1];
        }
        sg[tid] = __frcp_rn(1.f + __expf(-(m + s*(1.f/16384.f))));
    }
    __syncthreads();
    int pp = blockIdx.x * 256 + tid;
    float xv[32], yv[32];
    #pragma unroll
    for (int ci = 0; ci < 32; ci++) {
        xv[ci] = ox[((size_t)b*32 + ci)*16384 + pp];
        yv[ci] = oy[((size_t)b*32 + ci)*16384 + pp];
    }
    #pragma unroll 4
    for (int c = 0; c < 32; c++) {
        float r1 = 0.f, r2 = 0.f;
        #pragma unroll
        for (int q = 0; q < 8; q++) {
            float4 w4 = *reinterpret_cast<const float4*>(&sw[c*32 + q*4]);
            r1 = fmaf(w4.x, yv[q*4+0], r1); r2 = fmaf(w4.x, xv[q*4+0], r2);
            r1 = fmaf(w4.y, yv[q*4+1], r1); r2 = fmaf(w4.y, xv[q*4+1], r2);
            r1 = fmaf(w4.z, yv[q*4+2], r1); r2 = fmaf(w4.z, xv[q*4+2], r2);
            r1 = fmaf(w4.w, yv[q*4+3], r1); r2 = fmaf(w4.w, xv[q*4+3], r2);
        }
        size_t idx = ((size_t)b*32 + c)*16384 + pp;
        g_c2[idx] += sg[c]*r1 + sg[32+c]*r2;
    }
}

// ---------------- conv3 (32->1, 3x3) + sigmoid ----------------
__global__ void conv3_kernel(const float* __restrict__ w, const float* __restrict__ bias,
                             float* __restrict__ out) {
    __shared__ float sF[32][18][18];
    __shared__ float sw[288];
    int b = blockIdx.y;
    int tile = blockIdx.x;
    int ty0 = (tile >> 3) * 16, tx0 = (tile & 7) * 16;
    int tid = threadIdx.x;
    for (int idx = tid; idx < 32*324; idx += 256) {
        int ci = idx / 324; int rem = idx - ci*324;
        int r = rem / 18, c = rem - r*18;
        int gy = ty0 + r - 1, gx = tx0 + c - 1;
        float v = 0.f;
        if (gy >= 0 && gy < 128 && gx >= 0 && gx < 128)
            v = g_c2[(((size_t)b*32 + ci) << 14) + gy*128 + gx];
        sF[ci][r][c] = v;
    }
    for (int idx = tid; idx < 288; idx += 256) sw[idx] = w[idx];
    __syncthreads();
    int px = tid & 15, py = tid >> 4;
    float acc = bias[0];
    #pragma unroll 4
    for (int ci = 0; ci < 32; ci++)
        #pragma unroll
        for (int ky = 0; ky < 3; ky++)
            #pragma unroll
            for (int kx = 0; kx < 3; kx++)
                acc = fmaf(sw[ci*9 + ky*3 + kx], sF[ci][py + ky][px + kx], acc);
    out[((size_t)b << 14) + (ty0 + py)*128 + tx0 + px] = __frcp_rn(1.f + __expf(-acc));
}

// ---------------- launch ----------------
extern "C" void kernel_launch(void* const* d_in, const int* in_sizes, int n_in,
                              void* d_out, int out_size) {
    const float* fused_in = (const float*)d_in[0];
    const float* orig_x   = (const float*)d_in[1];
    const float* orig_y   = (const float*)d_in[2];
    const float* m_ln_g   = (const float*)d_in[3];
    const float* m_ln_b   = (const float*)d_in[4];
    const float* m_in_w   = (const float*)d_in[5];
    const float* m_conv_w = (const float*)d_in[6];
    const float* m_conv_b = (const float*)d_in[7];
    const float* m_xproj_w= (const float*)d_in[8];
    const float* m_dt_w   = (const float*)d_in[9];
    const float* m_dt_b   = (const float*)d_in[10];
    const float* m_Alog   = (const float*)d_in[11];
    const float* m_D      = (const float*)d_in[12];
    const float* m_out_w  = (const float*)d_in[13];
    const float* lnf_g    = (const float*)d_in[14];
    const float* lnf_b    = (const float*)d_in[15];
    const float* c1_w     = (const float*)d_in[16];
    const float* c1_b     = (const float*)d_in[17];
    const float* bn1_g    = (const float*)d_in[18];
    const float* bn1_b    = (const float*)d_in[19];
    const float* bn1_m    = (const float*)d_in[20];
    const float* bn1_v    = (const float*)d_in[21];
    const float* c2_w     = (const float*)d_in[22];
    const float* c2_b     = (const float*)d_in[23];
    const float* bn2_g    = (const float*)d_in[24];
    const float* bn2_b    = (const float*)d_in[25];
    const float* bn2_m    = (const float*)d_in[26];
    const float* bn2_v    = (const float*)d_in[27];
    const float* cce_w1   = (const float*)d_in[28];
    const float* cce_w2   = (const float*)d_in[29];
    const float* c3_w     = (const float*)d_in[30];
    const float* c3_b     = (const float*)d_in[31];
    float* out = (float*)d_out;

    float *p_fused, *p_h, *p_xz, *p_xm, *p_xdbl, *p_y, *p_img, *p_c1, *p_c2, *p_w1c, *p_w2c;
    cudaGetSymbolAddress((void**)&p_fused, g_fused);
    cudaGetSymbolAddress((void**)&p_h,     g_h);
    cudaGetSymbolAddress((void**)&p_xz,    g_xz);
    cudaGetSymbolAddress((void**)&p_xm,    g_xm);
    cudaGetSymbolAddress((void**)&p_xdbl,  g_xdbl);
    cudaGetSymbolAddress((void**)&p_y,     g_y);
    cudaGetSymbolAddress((void**)&p_img,   g_img);
    cudaGetSymbolAddress((void**)&p_c1,    g_c1);
    cudaGetSymbolAddress((void**)&p_c2,    g_c2);
    cudaGetSymbolAddress((void**)&p_w1c,   g_w1c);
    cudaGetSymbolAddress((void**)&p_w2c,   g_w2c);

    // launches 1-3: weight prep + first LN; #4 = cce_gate_part (profiled slot)
    make_wc_kernel<<<32, 256>>>(c1_w, p_w1c, 64*128);
    make_wc_kernel<<<8, 256>>>(c2_w, p_w2c, 32*64);
    ln_kernel<<<2048, 256>>>(fused_in, m_ln_g, m_ln_b, p_h);
    cce_gate_part<<<dim3(GSLAB, 16, 2), 256>>>(cce_w1, orig_x, orig_y);

    // ---- 3 Mamba blocks ----
    for (int i = 0; i < 3; i++) {
        const float* src = (i == 0) ? fused_in : p_fused;
        sgemm128<<<dim3(4, 128), 256>>>(p_h, m_in_w + (size_t)i*512*128, p_xz, 512, 128);
        dwconv_silu_kernel<<<16384, 256>>>(m_conv_w + i*DI*4, m_conv_b + i*DI);
        gemm_tn_kernel<<<dim3(1, 256), 256>>>(p_xm, m_xproj_w + (size_t)i*24*256, p_xdbl, 24, 256);
        scan_pass1<<<dim3(NSEG, 16), 256>>>(m_Alog + i*DI*8, m_dt_w + i*DI*8, m_dt_b + i*DI);
        scan_pass2<<<512, 256>>>();
        scan_pass3<<<dim3(NSEG, 16), 256>>>(m_Alog + i*DI*8, m_D + i*DI);
        int mode = (i < 2) ? 0 : 1;
        const float* gam = (i < 2) ? (m_ln_g + (i+1)*128) : m_ln_g;
        const float* bet = (i < 2) ? (m_ln_b + (i+1)*128) : m_ln_b;
        sgemm_out_ln<<<128, 256>>>(p_y, m_out_w + (size_t)i*128*256, src,
                                   gam, bet, p_fused, p_h, mode);
    }

    // ---- final LN -> NCHW image ----
    ln_final_kernel<<<2048, 256>>>(p_fused, lnf_g, lnf_b);

    // ---- conv1: up2 + 3x3 (128->64), bn, relu ----
    conv_up2_kernel<128, 64, 32, 64, 1><<<dim3(4, 8, 16), 256>>>(
        p_img, p_c1, p_w1c, c1_b, bn1_g, bn1_b, bn1_m, bn1_v);

    // ---- conv2: up2 + 3x3 (64->32), relu, bn ----
    conv_up2_kernel<64, 32, 64, 128, 2><<<dim3(16, 4, 16), 256>>>(
        p_c1, p_c2, p_w2c, c2_b, bn2_g, bn2_b, bn2_m, bn2_v);

    // ---- CCE apply (gates finalized in-kernel from partials) ----
    cce_apply_kernel<<<dim3(64, 16), 256>>>(cce_w2, orig_x, orig_y);

    // ---- conv3 + sigmoid -> output ----
    conv3_kernel<<<dim3(64, 16), 256>>>(c3_w, c3_b, out);
}